// round 11
// baseline (speedup 1.0000x reference)
#include <cuda_runtime.h>
#include <cuda_bf16.h>
#include <math.h>
#include <stdint.h>

#define B_  8
#define T_  1024
#define D_  768
#define H_  12
#define HD_ 64
#define BH_ (B_*H_)   /* 96 */
#define N_  (B_*T_)   /* 8192 */
#define WSZ_ ((size_t)D_*D_)
#define C_SM  (0.125f * 1.44269504088896340736f)   /* 0.125*log2(e) */
#define K8C   (1.44269504088896340736f)            /* log2(e) */

// ---- scratch (static device globals; no allocation) ----
__device__ uint32_t g_xhi[N_*D_];          // x tf32
__device__ uint32_t g_wqh[D_*D_];          // Wq tf32
__device__ uint32_t g_wkh[D_*D_];
__device__ uint32_t g_wvh[D_*D_];
__device__ __nv_bfloat16 g_woth[D_*D_];    // Wo^T bf16 hi [n][k]
__device__ __nv_bfloat16 g_wotl[D_*D_];    // Wo^T bf16 lo
__device__ uint32_t g_q[BH_*T_*HD_];       // tf32 (pre-scaled by C_SM), [bh][t][hd]
__device__ uint32_t g_k[BH_*T_*HD_];       // tf32, [bh][t][hd]
__device__ uint32_t g_v[BH_*T_*HD_];       // tf32, TRANSPOSED [bh][hd][t]
__device__ __nv_bfloat16 g_oh[N_*D_];      // attn out hi bf16, row-major
__device__ __nv_bfloat16 g_ol[N_*D_];      // attn out lo
__device__ float    g_ga1[BH_*T_];         // log2e * ga1
__device__ float    g_msk[N_];             // log2e * attn_mask  [b][t]
__device__ float    g_wg2[HD_*2];
__device__ float    g_bg2[2];

// ---- helpers ----
__device__ __forceinline__ uint32_t f2tf(float f) {
    uint32_t u;
    asm("cvt.rna.tf32.f32 %0, %1;" : "=r"(u) : "f"(f));
    return u;
}
__device__ __forceinline__ float ex2(float x) {
    float r;
    asm("ex2.approx.f32 %0, %1;" : "=f"(r) : "f"(x));
    return r;
}
__device__ __forceinline__ void mma_tf32(float* d, const uint32_t* a, const uint32_t* b) {
    asm volatile(
        "mma.sync.aligned.m16n8k8.row.col.f32.tf32.tf32.f32 "
        "{%0,%1,%2,%3}, {%4,%5,%6,%7}, {%8,%9}, {%0,%1,%2,%3};\n"
        : "+f"(d[0]), "+f"(d[1]), "+f"(d[2]), "+f"(d[3])
        : "r"(a[0]), "r"(a[1]), "r"(a[2]), "r"(a[3]), "r"(b[0]), "r"(b[1]));
}
__device__ __forceinline__ void mma_bf16(float* d, const uint32_t* a, const uint32_t* b) {
    asm volatile(
        "mma.sync.aligned.m16n8k16.row.col.f32.bf16.bf16.f32 "
        "{%0,%1,%2,%3}, {%4,%5,%6,%7}, {%8,%9}, {%0,%1,%2,%3};\n"
        : "+f"(d[0]), "+f"(d[1]), "+f"(d[2]), "+f"(d[3])
        : "r"(a[0]), "r"(a[1]), "r"(a[2]), "r"(a[3]), "r"(b[0]), "r"(b[1]));
}
#define LDSM_X4(r, a) \
    asm volatile("ldmatrix.sync.aligned.m8n8.x4.shared.b16 {%0,%1,%2,%3}, [%4];" \
        : "=r"((r)[0]), "=r"((r)[1]), "=r"((r)[2]), "=r"((r)[3]) : "r"(a))

__device__ __forceinline__ uint32_t saddr(const void* p) {
    return (uint32_t)__cvta_generic_to_shared(p);
}
__device__ __forceinline__ void cp16(uint32_t s, const void* g) {
    asm volatile("cp.async.cg.shared.global [%0], [%1], 16;\n" :: "r"(s), "l"(g));
}
#define CP_COMMIT() asm volatile("cp.async.commit_group;\n")
#define CP_WAIT2()  asm volatile("cp.async.wait_group 2;\n")
#define CP_WAIT1()  asm volatile("cp.async.wait_group 1;\n")
#define CP_WAIT0()  asm volatile("cp.async.wait_group 0;\n")

__device__ __forceinline__ void bfsplit(float f, __nv_bfloat16& h, __nv_bfloat16& l) {
    h = __float2bfloat16(f);
    l = __float2bfloat16(f - __bfloat162float(h));
}

// ============================================================
// conv_all: one kernel for all preconversion.
// ============================================================
#define NXB 6144
#define NWB 576
__global__ __launch_bounds__(256)
void conv_all(const float4* __restrict__ x,
              const float4* __restrict__ Wq, const float4* __restrict__ Wk,
              const float4* __restrict__ Wv, const float*  __restrict__ Wo,
              const float* __restrict__ Wg, const float* __restrict__ bg,
              uint4* __restrict__ xhi, uint4* __restrict__ wqh,
              uint4* __restrict__ wkh, uint4* __restrict__ wvh,
              __nv_bfloat16* __restrict__ woth, __nv_bfloat16* __restrict__ wotl)
{
    __shared__ float tile[32][33];
    const int bid = blockIdx.x, tid = threadIdx.x;

    if (bid == 0 && tid < 64) {
        int d = tid;
        const float* wg = Wg + d * 8;
        g_wg2[d * 2 + 0] = wg[0] + wg[1] + wg[2] + wg[3];
        g_wg2[d * 2 + 1] = wg[4] + wg[5] + wg[6] + wg[7];
        if (d == 0) {
            g_bg2[0] = bg[0] + bg[1] + bg[2] + bg[3];
            g_bg2[1] = bg[4] + bg[5] + bg[6] + bg[7];
        }
    }

    if (bid < NXB) {
        int i = bid * 256 + tid;
        float4 v = x[i];
        uint4 h;
        h.x = f2tf(v.x); h.y = f2tf(v.y); h.z = f2tf(v.z); h.w = f2tf(v.w);
        xhi[i] = h;
    } else if (bid < NXB + 3 * NWB) {
        int r = bid - NXB;
        int z = r / NWB;
        int i = (r % NWB) * 256 + tid;
        const float4* in = (z == 0) ? Wq : (z == 1) ? Wk : Wv;
        uint4* out = (z == 0) ? wqh : (z == 1) ? wkh : wvh;
        float4 v = in[i];
        uint4 h;
        h.x = f2tf(v.x); h.y = f2tf(v.y); h.z = f2tf(v.z); h.w = f2tf(v.w);
        out[i] = h;
    } else {
        int bx = bid - (NXB + 3 * NWB);
        int n0 = (bx % 24) * 32, k0 = (bx / 24) * 32;
        int tx = tid & 31, ty0 = tid >> 5;
#pragma unroll
        for (int j = 0; j < 4; j++)
            tile[ty0 + 8 * j][tx] = Wo[(size_t)(k0 + ty0 + 8 * j) * D_ + n0 + tx];
        __syncthreads();
#pragma unroll
        for (int j = 0; j < 4; j++) {
            int ty = ty0 + 8 * j;
            float f = tile[tx][ty];
            __nv_bfloat16 h, l;
            bfsplit(f, h, l);
            size_t o = (size_t)(n0 + ty) * D_ + k0 + tx;
            woth[o] = h; wotl[o] = l;
        }
    }
}

// ============================================================
// Gates: emits log2e*ga1 ; also pre-scales the mask.
// ============================================================
__global__ __launch_bounds__(256)
void gates_kernel(const float* __restrict__ x, const float* __restrict__ grep_a,
                  const float* __restrict__ attn_mask, float* __restrict__ ga1)
{
    int gidx = blockIdx.x * 256 + threadIdx.x;
    if (gidx < N_) g_msk[gidx] = K8C * attn_mask[gidx];

    int w    = blockIdx.x * 8 + (threadIdx.x >> 5);
    int lane = threadIdx.x & 31;
    int bh = w >> 10, t = w & 1023;
    int b = bh / H_, h = bh % H_;
    const float* xp = x + ((size_t)b * T_ + t) * D_ + h * HD_;

    float s0 = 0.f, s1 = 0.f;
#pragma unroll
    for (int d = lane; d < HD_; d += 32) {
        float xv = xp[d];
        s0 += xv * g_wg2[d * 2 + 0];
        s1 += xv * g_wg2[d * 2 + 1];
    }
#pragma unroll
    for (int off = 16; off > 0; off >>= 1) {
        s0 += __shfl_xor_sync(0xffffffffu, s0, off);
        s1 += __shfl_xor_sync(0xffffffffu, s1, off);
    }
    if (lane == 0) {
        s0 += g_bg2[0];
        s1 += g_bg2[1];
        float ga = 1.f / (1.f + expf(-s0));
        float gb = 1.f / (1.f + expf(-s1));
        ga1[w] = K8C * (ga * (gb * grep_a[h] - 1.f) + 2.f);
    }
}

// ============================================================
// Merged QKV GEMM (tf32, 1-term). Q pre-scaled by C_SM.
// q,k -> [bh][t][hd] ; v (z==2) -> TRANSPOSED [bh][hd][t].
// ============================================================
#define QKV_STAGE 4736
__global__ __launch_bounds__(256, 2)
void gemm_qkv(const uint32_t* __restrict__ A,
              const uint32_t* __restrict__ W0, const uint32_t* __restrict__ W1,
              const uint32_t* __restrict__ W2,
              const float* __restrict__ bb0, const float* __restrict__ bb1,
              const float* __restrict__ bb2,
              uint32_t* __restrict__ o0, uint32_t* __restrict__ o1,
              uint32_t* __restrict__ o2)
{
    extern __shared__ uint32_t sm[];
    const int z = blockIdx.z;
    const uint32_t* W = (z == 0) ? W0 : (z == 1) ? W1 : W2;
    const float* bias = (z == 0) ? bb0 : (z == 1) ? bb1 : bb2;
    uint32_t* out     = (z == 0) ? o0 : (z == 1) ? o1 : o2;
    const float oscale = (z == 0) ? C_SM : 1.f;

    const int tid = threadIdx.x;
    const int w = tid >> 5, lane = tid & 31, g = lane >> 2, q4 = lane & 3;
    const int wm = (w & 1) * 64, wn = (w >> 1) * 32;
    const int row0 = blockIdx.x * 128, col0 = blockIdx.y * 128;

    float acc[4][4][4];
#pragma unroll
    for (int i = 0; i < 4; i++)
#pragma unroll
        for (int f = 0; f < 4; f++)
#pragma unroll
            for (int e = 0; e < 4; e++) acc[i][f][e] = 0.f;

#define QKV_STAGE_LOAD(s, k0) do {                                             \
    uint32_t* As_ = sm + (s) * QKV_STAGE;                                      \
    uint32_t* Bs_ = As_ + 2560;                                                \
    _Pragma("unroll")                                                          \
    for (int i = 0; i < 2; i++) {                                              \
        int idx = tid + i * 256;                                               \
        int m = idx >> 2, kc = (idx & 3) * 4;                                  \
        cp16(saddr(&As_[m * 20 + kc]), A + (size_t)(row0 + m) * D_ + (k0) + kc); \
        int kk = idx >> 5, n4 = (idx & 31) * 4;                                \
        cp16(saddr(&Bs_[kk * 136 + n4]), W + (size_t)((k0) + kk) * D_ + col0 + n4); \
    } } while (0)

    QKV_STAGE_LOAD(0, 0);  CP_COMMIT();
    QKV_STAGE_LOAD(1, 16); CP_COMMIT();
    QKV_STAGE_LOAD(2, 32); CP_COMMIT();

    int st = 0;
    for (int kb = 0; kb < 48; kb++) {
        if (kb + 2 < 48) CP_WAIT2(); else CP_WAIT0();
        __syncthreads();
        const uint32_t* As = sm + st * QKV_STAGE;
        const uint32_t* Bs = As + 2560;
#pragma unroll
        for (int s = 0; s < 2; s++) {
            int kc = 8 * s + q4;
            uint32_t af[4][4], bf2[4][2];
#pragma unroll
            for (int i = 0; i < 4; i++) {
                int r = wm + 16 * i + g;
                af[i][0] = As[r * 20 + kc];       af[i][1] = As[(r + 8) * 20 + kc];
                af[i][2] = As[r * 20 + kc + 4];   af[i][3] = As[(r + 8) * 20 + kc + 4];
            }
#pragma unroll
            for (int f = 0; f < 4; f++) {
                int n = wn + 8 * f + g;
                bf2[f][0] = Bs[kc * 136 + n];
                bf2[f][1] = Bs[(kc + 4) * 136 + n];
            }
#pragma unroll
            for (int i = 0; i < 4; i++)
#pragma unroll
                for (int f = 0; f < 4; f++) mma_tf32(acc[i][f], af[i], bf2[f]);
        }
        __syncthreads();
        if (kb + 3 < 48) { QKV_STAGE_LOAD(st, (kb + 3) * 16); CP_COMMIT(); }
        st++; if (st == 3) st = 0;
    }

    // epilogue
#pragma unroll
    for (int i = 0; i < 4; i++)
#pragma unroll
        for (int f = 0; f < 4; f++) {
            int col = col0 + wn + 8 * f + 2 * q4;
            float b0 = bias[col], b1 = bias[col + 1];
            int hh = col >> 6, hd = col & 63;
#pragma unroll
            for (int half = 0; half < 2; half++) {
                int row = row0 + wm + 16 * i + g + 8 * half;
                int bb = row >> 10, tt = row & 1023;
                uint32_t u0 = f2tf((acc[i][f][2 * half + 0] + b0) * oscale);
                uint32_t u1 = f2tf((acc[i][f][2 * half + 1] + b1) * oscale);
                if (z == 2) {
                    uint32_t* dst = out + (size_t)(bb * H_ + hh) * HD_ * T_ + tt;
                    dst[(size_t)hd * T_]       = u0;
                    dst[(size_t)(hd + 1) * T_] = u1;
                } else {
                    uint2 u; u.x = u0; u.y = u1;
                    *(uint2*)(out + ((size_t)(bb * H_ + hh) * T_ + tt) * HD_ + hd) = u;
                }
            }
        }
}

// ============================================================
// Flash attention, static softmax, ldmatrix fragment loads.
// stage (words): Ks 32x68=2176 + Vt 64x36=2304 + RB 32x132=4224 = 8704
//  x2 stages = 17408 ; Pp 128x36 = 4608 ; Ms 1024 => 23040 w = 92160 B
// ============================================================
#define ATT_STAGE 8704
__global__ __launch_bounds__(256, 2)
void attn_kernel(const float* __restrict__ rel_bias)
{
    extern __shared__ float smf[];
    uint32_t* Pp = (uint32_t*)(smf + 2 * ATT_STAGE);   // [128][36]
    float*    Ms = smf + 2 * ATT_STAGE + 4608;         // [1024] pre-scaled mask

    const int tid  = threadIdx.x;
    const int w    = tid >> 5;
    const int lane = tid & 31;
    const int g    = lane >> 2;
    const int q4   = lane & 3;
    const int qb   = 16 * w;
    const int q0   = blockIdx.x * 128;
    const int bh   = blockIdx.y;
    const int b    = bh / H_, h = bh % H_;

    const uint32_t* qptr  = g_q + (size_t)bh * T_ * HD_;
    const uint32_t* kptr  = g_k + (size_t)bh * T_ * HD_;
    const uint32_t* vtptr = g_v + (size_t)bh * HD_ * T_;   // [hd][t]

    const int r0 = qb + g;
    const int r1 = qb + g + 8;

#define ATT_STAGE_LOAD(s, k0) do {                                             \
    uint32_t* Ks_ = (uint32_t*)(smf + (s) * ATT_STAGE);                        \
    uint32_t* Vt_ = Ks_ + 2176;                                                \
    float*    RB_ = smf + (s) * ATT_STAGE + 4480;                              \
    _Pragma("unroll")                                                          \
    for (int i = 0; i < 2; i++) {                                              \
        int idx = tid + i * 256;                                               \
        int kk = idx >> 4, d4 = (idx & 15) * 4;                                \
        cp16(saddr(&Ks_[kk * 68 + d4]), kptr + (size_t)((k0) + kk) * HD_ + d4);\
        int hd = idx >> 3, ch = (idx & 7) * 4;                                 \
        cp16(saddr(&Vt_[hd * 36 + ch]), vtptr + (size_t)hd * T_ + (k0) + ch);  \
    }                                                                          \
    const float* rbp_ = rel_bias + ((size_t)bh * T_ + (k0)) * T_ + q0;         \
    _Pragma("unroll")                                                          \
    for (int i = 0; i < 4; i++) {                                              \
        int idx = tid + i * 256;                                               \
        int kk = idx >> 5, qq = (idx & 31) * 4;                                \
        cp16(saddr(&RB_[kk * 132 + qq]), rbp_ + (size_t)kk * T_ + qq);         \
    } } while (0)

    ATT_STAGE_LOAD(0, 0);
    cp16(saddr(&Ms[tid * 4]), g_msk + (size_t)b * T_ + tid * 4);
    CP_COMMIT();
    ATT_STAGE_LOAD(1, 32);
    CP_COMMIT();

    uint32_t qf[8][4];
    {
        const uint32_t* qa = qptr + (size_t)(q0 + r0) * HD_;
        const uint32_t* qc = qptr + (size_t)(q0 + r1) * HD_;
#pragma unroll
        for (int s = 0; s < 8; s++) {
            qf[s][0] = qa[q4 + 8 * s];
            qf[s][1] = qc[q4 + 8 * s];
            qf[s][2] = qa[q4 + 4 + 8 * s];
            qf[s][3] = qc[q4 + 4 + 8 * s];
        }
    }
    const float ga0  = g_ga1[(size_t)bh * T_ + q0 + r0];
    const float ga1v = g_ga1[(size_t)bh * T_ + q0 + r1];

    // ldmatrix lane-address offsets (within current stage, added per use)
    // P address: fixed for the whole kernel
    const uint32_t paddr = saddr(&Pp[(qb + (lane & 7) + 8 * ((lane >> 3) & 1)) * 36
                                     + 4 * (lane >> 4)]);

    float l0 = 0.f, l1 = 0.f;
    float oacc[8][4];
#pragma unroll
    for (int f = 0; f < 8; f++)
#pragma unroll
        for (int e = 0; e < 4; e++) oacc[f][e] = 0.f;

    for (int kt = 0; kt < 32; kt++) {
        if (kt + 1 < 32) CP_WAIT1(); else CP_WAIT0();
        __syncthreads();
        const int cur = kt & 1;
        const uint32_t* Ks = (const uint32_t*)(smf + cur * ATT_STAGE);
        const uint32_t* Vt = Ks + 2176;
        const float*    RB = smf + cur * ATT_STAGE + 4480;
        const int k0 = kt * 32;

        const uint32_t kbase = saddr(&Ks[lane * 68]);
        const uint32_t va0   = saddr(&Vt[lane * 36]);
        const uint32_t va1   = saddr(&Vt[(32 + lane) * 36]);

        // ---- S_log2 init: ga'*rb + mask' ----
        float sacc[4][4];
#pragma unroll
        for (int f = 0; f < 4; f++) {
            int c0 = 8 * f + 2 * q4;
            sacc[f][0] = fmaf(ga0,  RB[c0 * 132 + r0],       Ms[k0 + c0]);
            sacc[f][1] = fmaf(ga0,  RB[(c0 + 1) * 132 + r0], Ms[k0 + c0 + 1]);
            sacc[f][2] = fmaf(ga1v, RB[c0 * 132 + r1],       Ms[k0 + c0]);
            sacc[f][3] = fmaf(ga1v, RB[(c0 + 1) * 132 + r1], Ms[k0 + c0 + 1]);
        }
        // ---- QK via ldmatrix K fragments ----
#pragma unroll
        for (int s = 0; s < 8; s++) {
            uint32_t bfA[4], bfB[4];
            LDSM_X4(bfA, kbase + (8 * s) * 4);
            LDSM_X4(bfB, kbase + (8 * s + 4) * 4);
#pragma unroll
            for (int f = 0; f < 4; f++) {
                uint32_t bb2[2] = { bfA[f], bfB[f] };
                mma_tf32(sacc[f], qf[s], bb2);
            }
        }

        // ---- static softmax: P = exp2(S); accumulate partial l ----
#pragma unroll
        for (int f = 0; f < 4; f++) {
            sacc[f][0] = ex2(sacc[f][0]);
            sacc[f][1] = ex2(sacc[f][1]);
            sacc[f][2] = ex2(sacc[f][2]);
            sacc[f][3] = ex2(sacc[f][3]);
            l0 += sacc[f][0] + sacc[f][1];
            l1 += sacc[f][2] + sacc[f][3];
        }

        // ---- stage P (tf32) ----
#pragma unroll
        for (int f = 0; f < 4; f++) {
            int c0 = 8 * f + 2 * q4;
            Pp[r0 * 36 + c0]     = f2tf(sacc[f][0]);
            Pp[r0 * 36 + c0 + 1] = f2tf(sacc[f][1]);
            Pp[r1 * 36 + c0]     = f2tf(sacc[f][2]);
            Pp[r1 * 36 + c0 + 1] = f2tf(sacc[f][3]);
        }
        __syncwarp();

        // ---- O += P @ V via ldmatrix (P as A-frag, Vt as B-frags) ----
#pragma unroll
        for (int s = 0; s < 4; s++) {
            uint32_t pa[4], v0[4], v1[4], v2[4], v3[4];
            LDSM_X4(pa, paddr + (8 * s) * 4);
            LDSM_X4(v0, va0 + (8 * s) * 4);
            LDSM_X4(v2, va0 + (8 * s + 4) * 4);
            LDSM_X4(v1, va1 + (8 * s) * 4);
            LDSM_X4(v3, va1 + (8 * s + 4) * 4);
#pragma unroll
            for (int f = 0; f < 4; f++) {
                uint32_t vb[2] = { v0[f], v2[f] };
                mma_tf32(oacc[f], pa, vb);
            }
#pragma unroll
            for (int f = 0; f < 4; f++) {
                uint32_t vb[2] = { v1[f], v3[f] };
                mma_tf32(oacc[4 + f], pa, vb);
            }
        }
        __syncthreads();
        if (kt + 2 < 32) { ATT_STAGE_LOAD(cur, (kt + 2) * 32); CP_COMMIT(); }
    }

    // ---- reduce l across quad, finalize ----
    l0 += __shfl_xor_sync(0xffffffffu, l0, 1);
    l0 += __shfl_xor_sync(0xffffffffu, l0, 2);
    l1 += __shfl_xor_sync(0xffffffffu, l1, 1);
    l1 += __shfl_xor_sync(0xffffffffu, l1, 2);
    float inv0 = 1.f / l0, inv1 = 1.f / l1;
#pragma unroll
    for (int f = 0; f < 8; f++) {
        int c = 8 * f + 2 * q4;
        size_t i0 = ((size_t)b * T_ + q0 + r0) * D_ + h * HD_ + c;
        size_t i1 = ((size_t)b * T_ + q0 + r1) * D_ + h * HD_ + c;
        float v00 = oacc[f][0] * inv0, v01 = oacc[f][1] * inv0;
        float v10 = oacc[f][2] * inv1, v11 = oacc[f][3] * inv1;
        __nv_bfloat16 h00,l00,h01,l01,h10,l10,h11,l11;
        bfsplit(v00,h00,l00); bfsplit(v01,h01,l01);
        bfsplit(v10,h10,l10); bfsplit(v11,h11,l11);
        *(__nv_bfloat162*)(g_oh + i0) = {h00, h01};
        *(__nv_bfloat162*)(g_ol + i0) = {l00, l01};
        *(__nv_bfloat162*)(g_oh + i1) = {h10, h11};
        *(__nv_bfloat162*)(g_ol + i1) = {l10, l11};
    }
}

// ============================================================
// O-proj GEMM, bf16 3-term with ldmatrix (proven kernel).
// ============================================================
#define OB_STAGE 40960
__global__ __launch_bounds__(256, 2)
void gemm_o3(const __nv_bfloat16* __restrict__ Ah, const __nv_bfloat16* __restrict__ Al,
             const __nv_bfloat16* __restrict__ Bh, const __nv_bfloat16* __restrict__ Bl,
             const float* __restrict__ bias, float* __restrict__ out)
{
    extern __shared__ char smo[];
    const int tid = threadIdx.x;
    const int w = tid >> 5, lane = tid & 31, g = lane >> 2, q4 = lane & 3;
    const int wm = (w & 1) * 64, wn = (w >> 1) * 32;
    const int row0 = blockIdx.x * 128, col0 = blockIdx.y * 128;

    float acc[4][4][4];
#pragma unroll
    for (int i = 0; i < 4; i++)
#pragma unroll
        for (int f = 0; f < 4; f++)
#pragma unroll
            for (int e = 0; e < 4; e++) acc[i][f][e] = 0.f;

    const int lrow = lane & 15;
    const int lchk = (lane >> 4) * 16;

#define O3_STAGE_LOAD(s, k0) do {                                              \
    char* base_ = smo + (s) * OB_STAGE;                                        \
    _Pragma("unroll")                                                          \
    for (int i = 0; i < 2; i++) {                                              \
        int idx = tid + i * 256;                                               \
        int r = idx >> 2, ch = idx & 3;                                        \
        uint32_t so = saddr(base_ + r * 80 + ch * 16);                         \
        cp16(so,         Ah + (size_t)(row0 + r) * D_ + (k0) + ch * 8);        \
        cp16(so + 10240, Al + (size_t)(row0 + r) * D_ + (k0) + ch * 8);        \
        cp16(so + 20480, Bh + (size_t)(col0 + r) * D_ + (k0) + ch * 8);        \
        cp16(so + 30720, Bl + (size_t)(col0 + r) * D_ + (k0) + ch * 8);        \
    } } while (0)

    O3_STAGE_LOAD(0, 0);  CP_COMMIT();
    O3_STAGE_LOAD(1, 32); CP_COMMIT();

    for (int kb = 0; kb < 24; kb++) {
        if (kb + 1 < 24) CP_WAIT1(); else CP_WAIT0();
        __syncthreads();
        char* base = smo + (kb & 1) * OB_STAGE;
#pragma unroll
        for (int ks = 0; ks < 2; ks++) {
            uint32_t ah[4][4], al[4][4];
#pragma unroll
            for (int i = 0; i < 4; i++) {
                uint32_t a = saddr(base + (wm + 16 * i + lrow) * 80 + ks * 32 + lchk);
                LDSM_X4(ah[i], a);
                LDSM_X4(al[i], a + 10240);
            }
            uint32_t bh4[2][4], bl4[2][4];
#pragma unroll
            for (int j = 0; j < 2; j++) {
                uint32_t a = saddr(base + 20480 + (wn + 16 * j + lrow) * 80 + ks * 32 + lchk);
                LDSM_X4(bh4[j], a);
                LDSM_X4(bl4[j], a + 10240);
            }
#pragma unroll
            for (int i = 0; i < 4; i++)
#pragma unroll
                for (int f = 0; f < 4; f++) {
                    uint32_t bhf[2] = { bh4[f >> 1][f & 1], bh4[f >> 1][(f & 1) + 2] };
                    uint32_t blf[2] = { bl4[f >> 1][f & 1], bl4[f >> 1][(f & 1) + 2] };
                    mma_bf16(acc[i][f], ah[i], bhf);
                    mma_bf16(acc[i][f], ah[i], blf);
                    mma_bf16(acc[i][f], al[i], bhf);
                }
        }
        __syncthreads();
        if (kb + 2 < 24) { O3_STAGE_LOAD(kb & 1, (kb + 2) * 32); CP_COMMIT(); }
    }

#pragma unroll
    for (int i = 0; i < 4; i++)
#pragma unroll
        for (int f = 0; f < 4; f++) {
            int col = col0 + wn + 8 * f + 2 * q4;
            float b0 = bias[col], b1 = bias[col + 1];
#pragma unroll
            for (int half = 0; half < 2; half++) {
                int row = row0 + wm + 16 * i + g + 8 * half;
                float2 v;
                v.x = acc[i][f][2 * half + 0] + b0;
                v.y = acc[i][f][2 * half + 1] + b1;
                *(float2*)(out + (size_t)row * D_ + col) = v;
            }
        }
}

// ============================================================
extern "C" void kernel_launch(void* const* d_in, const int* in_sizes, int n_in,
                              void* d_out, int out_size)
{
    const float* x         = (const float*)d_in[0];
    const float* attn_mask = (const float*)d_in[1];
    const float* rel_bias  = (const float*)d_in[2];
    const float* Wq = (const float*)d_in[3];
    const float* bq = (const float*)d_in[4];
    const float* Wk = (const float*)d_in[5];
    const float* bk = (const float*)d_in[6];
    const float* Wv = (const float*)d_in[7];
    const float* bv = (const float*)d_in[8];
    const float* Wo = (const float*)d_in[9];
    const float* bo = (const float*)d_in[10];
    const float* Wg = (const float*)d_in[11];
    const float* bg = (const float*)d_in[12];
    const float* grep_a = (const float*)d_in[13];
    float* out = (float*)d_out;

    uint32_t *xhi, *wqh, *wkh, *wvh, *q, *k, *v;
    __nv_bfloat16 *woth, *wotl, *oh, *ol;
    float *ga1;
    cudaGetSymbolAddress((void**)&xhi,  g_xhi);
    cudaGetSymbolAddress((void**)&wqh,  g_wqh);
    cudaGetSymbolAddress((void**)&wkh,  g_wkh);
    cudaGetSymbolAddress((void**)&wvh,  g_wvh);
    cudaGetSymbolAddress((void**)&woth, g_woth);
    cudaGetSymbolAddress((void**)&wotl, g_wotl);
    cudaGetSymbolAddress((void**)&q,    g_q);
    cudaGetSymbolAddress((void**)&k,    g_k);
    cudaGetSymbolAddress((void**)&v,    g_v);
    cudaGetSymbolAddress((void**)&oh,   g_oh);
    cudaGetSymbolAddress((void**)&ol,   g_ol);
    cudaGetSymbolAddress((void**)&ga1,  g_ga1);

    cudaFuncSetAttribute(gemm_qkv,    cudaFuncAttributeMaxDynamicSharedMemorySize, QKV_STAGE * 3 * 4);
    cudaFuncSetAttribute(attn_kernel, cudaFuncAttributeMaxDynamicSharedMemorySize, 92160);
    cudaFuncSetAttribute(gemm_o3,     cudaFuncAttributeMaxDynamicSharedMemorySize, OB_STAGE * 2);

    conv_all<<<NXB + 3 * NWB + NWB, 256>>>(                                            // 0
        (const float4*)x, (const float4*)Wq, (const float4*)Wk, (const float4*)Wv,
        Wo, Wg, bg,
        (uint4*)xhi, (uint4*)wqh, (uint4*)wkh, (uint4*)wvh, woth, wotl);
    gates_kernel<<<BH_ * T_ / 8, 256>>>(x, grep_a, attn_mask, ga1);                     // 1
    gemm_qkv<<<dim3(64, 6, 3), 256, QKV_STAGE * 3 * 4>>>(                               // 2
        xhi, wqh, wkh, wvh, bq, bk, bv, q, k, v);
    attn_kernel<<<dim3(T_ / 128, BH_), 256, 92160>>>(rel_bias);                         // 3
    gemm_o3<<<dim3(64, 6), 256, OB_STAGE * 2>>>(oh, ol, woth, wotl, bo, out);           // 4
}

// round 12
// speedup vs baseline: 1.3547x; 1.3547x over previous
#include <cuda_runtime.h>
#include <cuda_bf16.h>
#include <cuda_fp16.h>
#include <math.h>
#include <stdint.h>

#define B_  8
#define T_  1024
#define D_  768
#define H_  12
#define HD_ 64
#define BH_ (B_*H_)   /* 96 */
#define N_  (B_*T_)   /* 8192 */
#define WSZ_ ((size_t)D_*D_)
#define C_SM  (0.125f * 1.44269504088896340736f)   /* 0.125*log2(e) */
#define K8C   (1.44269504088896340736f)            /* log2(e) */

// ---- scratch (static device globals; no allocation) ----
__device__ __half g_x16[N_*D_];            // x fp16
__device__ __half g_wt16[3][D_*D_];        // Wq/Wk/Wv^T fp16 [n][k]
__device__ __nv_bfloat16 g_woth[D_*D_];    // Wo^T bf16 hi [n][k]
__device__ __nv_bfloat16 g_wotl[D_*D_];    // Wo^T bf16 lo
__device__ __half g_q[BH_*T_*HD_];         // fp16 (pre-scaled C_SM), [bh][t][hd]
__device__ __half g_k[BH_*T_*HD_];         // fp16, [bh][t][hd]
__device__ __half g_v[BH_*T_*HD_];         // fp16, TRANSPOSED [bh][hd][t]
__device__ __nv_bfloat16 g_oh[N_*D_];      // attn out hi bf16, row-major
__device__ __nv_bfloat16 g_ol[N_*D_];      // attn out lo
__device__ float    g_ga1[BH_*T_];         // log2e * ga1
__device__ float    g_msk[N_];             // log2e * attn_mask
__device__ float    g_wg2[HD_*2];
__device__ float    g_bg2[2];

// ---- helpers ----
__device__ __forceinline__ float ex2(float x) {
    float r;
    asm("ex2.approx.f32 %0, %1;" : "=f"(r) : "f"(x));
    return r;
}
__device__ __forceinline__ void mma_f16(float* d, const uint32_t* a, const uint32_t* b) {
    asm volatile(
        "mma.sync.aligned.m16n8k16.row.col.f32.f16.f16.f32 "
        "{%0,%1,%2,%3}, {%4,%5,%6,%7}, {%8,%9}, {%0,%1,%2,%3};\n"
        : "+f"(d[0]), "+f"(d[1]), "+f"(d[2]), "+f"(d[3])
        : "r"(a[0]), "r"(a[1]), "r"(a[2]), "r"(a[3]), "r"(b[0]), "r"(b[1]));
}
__device__ __forceinline__ void mma_bf16(float* d, const uint32_t* a, const uint32_t* b) {
    asm volatile(
        "mma.sync.aligned.m16n8k16.row.col.f32.bf16.bf16.f32 "
        "{%0,%1,%2,%3}, {%4,%5,%6,%7}, {%8,%9}, {%0,%1,%2,%3};\n"
        : "+f"(d[0]), "+f"(d[1]), "+f"(d[2]), "+f"(d[3])
        : "r"(a[0]), "r"(a[1]), "r"(a[2]), "r"(a[3]), "r"(b[0]), "r"(b[1]));
}
#define LDSM_X4(r, a) \
    asm volatile("ldmatrix.sync.aligned.m8n8.x4.shared.b16 {%0,%1,%2,%3}, [%4];" \
        : "=r"((r)[0]), "=r"((r)[1]), "=r"((r)[2]), "=r"((r)[3]) : "r"(a))

__device__ __forceinline__ uint32_t saddr(const void* p) {
    return (uint32_t)__cvta_generic_to_shared(p);
}
__device__ __forceinline__ void cp16(uint32_t s, const void* g) {
    asm volatile("cp.async.cg.shared.global [%0], [%1], 16;\n" :: "r"(s), "l"(g));
}
#define CP_COMMIT() asm volatile("cp.async.commit_group;\n")
#define CP_WAIT1()  asm volatile("cp.async.wait_group 1;\n")
#define CP_WAIT0()  asm volatile("cp.async.wait_group 0;\n")

__device__ __forceinline__ void bfsplit(float f, __nv_bfloat16& h, __nv_bfloat16& l) {
    h = __float2bfloat16(f);
    l = __float2bfloat16(f - __bfloat162float(h));
}

// ============================================================
// conv_all: x -> fp16 ; Wq/Wk/Wv -> W^T fp16 ; Wo -> W^T bf16 hi/lo;
// block 0: Wg row-sums.
// ============================================================
#define NXB 6144
#define NTB 576
__global__ __launch_bounds__(256)
void conv_all(const float4* __restrict__ x,
              const float* __restrict__ Wq, const float* __restrict__ Wk,
              const float* __restrict__ Wv, const float* __restrict__ Wo,
              const float* __restrict__ Wg, const float* __restrict__ bg,
              __half* __restrict__ x16, __half* __restrict__ wt16,
              __nv_bfloat16* __restrict__ woth, __nv_bfloat16* __restrict__ wotl)
{
    __shared__ float tile[32][33];
    const int bid = blockIdx.x, tid = threadIdx.x;

    if (bid == 0 && tid < 64) {
        int d = tid;
        const float* wg = Wg + d * 8;
        g_wg2[d * 2 + 0] = wg[0] + wg[1] + wg[2] + wg[3];
        g_wg2[d * 2 + 1] = wg[4] + wg[5] + wg[6] + wg[7];
        if (d == 0) {
            g_bg2[0] = bg[0] + bg[1] + bg[2] + bg[3];
            g_bg2[1] = bg[4] + bg[5] + bg[6] + bg[7];
        }
    }

    if (bid < NXB) {
        int i = bid * 256 + tid;
        float4 v = x[i];
        __half2 h0 = __floats2half2_rn(v.x, v.y);
        __half2 h1 = __floats2half2_rn(v.z, v.w);
        *(__half2*)(x16 + (size_t)i * 4)     = h0;
        *(__half2*)(x16 + (size_t)i * 4 + 2) = h1;
    } else {
        int r = bid - NXB;
        int z = r / NTB;                 // 0..3
        int bx = r % NTB;
        int n0 = (bx % 24) * 32, k0 = (bx / 24) * 32;
        const float* W = (z == 0) ? Wq : (z == 1) ? Wk : (z == 2) ? Wv : Wo;
        int tx = tid & 31, ty0 = tid >> 5;
#pragma unroll
        for (int j = 0; j < 4; j++)
            tile[ty0 + 8 * j][tx] = W[(size_t)(k0 + ty0 + 8 * j) * D_ + n0 + tx];
        __syncthreads();
#pragma unroll
        for (int j = 0; j < 4; j++) {
            int ty = ty0 + 8 * j;
            float f = tile[tx][ty];
            size_t o = (size_t)(n0 + ty) * D_ + k0 + tx;
            if (z < 3) {
                wt16[(size_t)z * WSZ_ + o] = __float2half(f);
            } else {
                __nv_bfloat16 h, l;
                bfsplit(f, h, l);
                woth[o] = h; wotl[o] = l;
            }
        }
    }
}

// ============================================================
// Gates: emits log2e*ga1 ; also pre-scales the mask.
// ============================================================
__global__ __launch_bounds__(256)
void gates_kernel(const float* __restrict__ x, const float* __restrict__ grep_a,
                  const float* __restrict__ attn_mask, float* __restrict__ ga1)
{
    int gidx = blockIdx.x * 256 + threadIdx.x;
    if (gidx < N_) g_msk[gidx] = K8C * attn_mask[gidx];

    int w    = blockIdx.x * 8 + (threadIdx.x >> 5);
    int lane = threadIdx.x & 31;
    int bh = w >> 10, t = w & 1023;
    int b = bh / H_, h = bh % H_;
    const float* xp = x + ((size_t)b * T_ + t) * D_ + h * HD_;

    float s0 = 0.f, s1 = 0.f;
#pragma unroll
    for (int d = lane; d < HD_; d += 32) {
        float xv = xp[d];
        s0 += xv * g_wg2[d * 2 + 0];
        s1 += xv * g_wg2[d * 2 + 1];
    }
#pragma unroll
    for (int off = 16; off > 0; off >>= 1) {
        s0 += __shfl_xor_sync(0xffffffffu, s0, off);
        s1 += __shfl_xor_sync(0xffffffffu, s1, off);
    }
    if (lane == 0) {
        s0 += g_bg2[0];
        s1 += g_bg2[1];
        float ga = 1.f / (1.f + expf(-s0));
        float gb = 1.f / (1.f + expf(-s1));
        ga1[w] = K8C * (ga * (gb * grep_a[h] - 1.f) + 2.f);
    }
}

// ============================================================
// QKV GEMM, fp16 1-term, ldmatrix (gemm_o3 skeleton).
// A = x16 [m][k] fp16 ; B = W^T [n][k] fp16.
// q,k -> [bh][t][hd] fp16 (q scaled C_SM) ; v -> [bh][hd][t] fp16.
// stage: A 128x80B (10240) + B 128x80B = 20480 B ; x2 stages.
// ============================================================
#define Q16_STAGE 20480
__global__ __launch_bounds__(256, 2)
void gemm_qkv16(const __half* __restrict__ A, const __half* __restrict__ WT,
                const float* __restrict__ bb0, const float* __restrict__ bb1,
                const float* __restrict__ bb2,
                __half* __restrict__ o0, __half* __restrict__ o1,
                __half* __restrict__ o2)
{
    extern __shared__ char smq[];
    const int z = blockIdx.z;
    const __half* B = WT + (size_t)z * WSZ_;
    const float* bias = (z == 0) ? bb0 : (z == 1) ? bb1 : bb2;
    __half* out       = (z == 0) ? o0 : (z == 1) ? o1 : o2;
    const float oscale = (z == 0) ? C_SM : 1.f;

    const int tid = threadIdx.x;
    const int w = tid >> 5, lane = tid & 31, g = lane >> 2, q4 = lane & 3;
    const int wm = (w & 1) * 64, wn = (w >> 1) * 32;
    const int row0 = blockIdx.x * 128, col0 = blockIdx.y * 128;

    float acc[4][4][4];
#pragma unroll
    for (int i = 0; i < 4; i++)
#pragma unroll
        for (int f = 0; f < 4; f++)
#pragma unroll
            for (int e = 0; e < 4; e++) acc[i][f][e] = 0.f;

    const int lrow = lane & 15;
    const int lchk = (lane >> 4) * 16;

#define Q16_STAGE_LOAD(s, k0) do {                                             \
    char* base_ = smq + (s) * Q16_STAGE;                                       \
    _Pragma("unroll")                                                          \
    for (int i = 0; i < 2; i++) {                                              \
        int idx = tid + i * 256;                                               \
        int r = idx >> 2, ch = idx & 3;                                        \
        uint32_t so = saddr(base_ + r * 80 + ch * 16);                         \
        cp16(so,         A + (size_t)(row0 + r) * D_ + (k0) + ch * 8);         \
        cp16(so + 10240, B + (size_t)(col0 + r) * D_ + (k0) + ch * 8);         \
    } } while (0)

    Q16_STAGE_LOAD(0, 0);  CP_COMMIT();
    Q16_STAGE_LOAD(1, 32); CP_COMMIT();

    for (int kb = 0; kb < 24; kb++) {
        if (kb + 1 < 24) CP_WAIT1(); else CP_WAIT0();
        __syncthreads();
        char* base = smq + (kb & 1) * Q16_STAGE;
#pragma unroll
        for (int ks = 0; ks < 2; ks++) {
            uint32_t ah[4][4], bh4[2][4];
#pragma unroll
            for (int i = 0; i < 4; i++)
                LDSM_X4(ah[i], saddr(base + (wm + 16 * i + lrow) * 80 + ks * 32 + lchk));
#pragma unroll
            for (int j = 0; j < 2; j++)
                LDSM_X4(bh4[j], saddr(base + 10240 + (wn + 16 * j + lrow) * 80 + ks * 32 + lchk));
#pragma unroll
            for (int i = 0; i < 4; i++)
#pragma unroll
                for (int f = 0; f < 4; f++) {
                    uint32_t bf2[2] = { bh4[f >> 1][f & 1], bh4[f >> 1][(f & 1) + 2] };
                    mma_f16(acc[i][f], ah[i], bf2);
                }
        }
        __syncthreads();
        if (kb + 2 < 24) { Q16_STAGE_LOAD(kb & 1, (kb + 2) * 32); CP_COMMIT(); }
    }

    // epilogue: (+bias)*oscale -> fp16, head layout (v transposed)
#pragma unroll
    for (int i = 0; i < 4; i++)
#pragma unroll
        for (int f = 0; f < 4; f++) {
            int col = col0 + wn + 8 * f + 2 * q4;
            float b0 = bias[col], b1 = bias[col + 1];
            int hh = col >> 6, hd = col & 63;
#pragma unroll
            for (int half = 0; half < 2; half++) {
                int row = row0 + wm + 16 * i + g + 8 * half;
                int bb = row >> 10, tt = row & 1023;
                float v0 = (acc[i][f][2 * half + 0] + b0) * oscale;
                float v1 = (acc[i][f][2 * half + 1] + b1) * oscale;
                if (z == 2) {
                    __half* dst = out + (size_t)(bb * H_ + hh) * HD_ * T_ + tt;
                    dst[(size_t)hd * T_]       = __float2half(v0);
                    dst[(size_t)(hd + 1) * T_] = __float2half(v1);
                } else {
                    *(__half2*)(out + ((size_t)(bb * H_ + hh) * T_ + tt) * HD_ + hd)
                        = __floats2half2_rn(v0, v1);
                }
            }
        }
}

// ============================================================
// Flash attention, fp16 operands (RB/mask/softmax/acc fp32).
// stage: Ks 32x144B (4608) + Vt 64x80B (5120) + RB 32x132w (16896) = 26624 B
//  x2 stages = 53248 ; P 128x80B = 10240 ; Ms 4096  => 67584 B
// ============================================================
#define ATT_STAGE_B 26624
__global__ __launch_bounds__(256, 2)
void attn_kernel(const float* __restrict__ rel_bias)
{
    extern __shared__ char smc[];
    uint32_t* Pp = (uint32_t*)(smc + 2 * ATT_STAGE_B);    // [128] rows x 20 words
    float*    Ms = (float*)(smc + 2 * ATT_STAGE_B + 10240);

    const int tid  = threadIdx.x;
    const int w    = tid >> 5;
    const int lane = tid & 31;
    const int g    = lane >> 2;
    const int q4   = lane & 3;
    const int qb   = 16 * w;
    const int q0   = blockIdx.x * 128;
    const int bh   = blockIdx.y;
    const int b    = bh / H_, h = bh % H_;

    const __half* qh  = g_q + (size_t)bh * T_ * HD_;
    const __half* kh  = g_k + (size_t)bh * T_ * HD_;
    const __half* vth = g_v + (size_t)bh * HD_ * T_;   // [hd][t]

    const int r0 = qb + g;
    const int r1 = qb + g + 8;

#define ATT_STAGE_LOAD(s, k0) do {                                             \
    char*  Ks_ = smc + (s) * ATT_STAGE_B;                                      \
    char*  Vt_ = Ks_ + 4608;                                                   \
    float* RB_ = (float*)(Ks_ + 9728);                                         \
    {   /* K: 32 rows x 8 chunks ; V: 64 rows x 4 chunks (1 each/thread) */    \
        int kk = tid >> 3, ch = tid & 7;                                       \
        cp16(saddr(Ks_ + kk * 144 + ch * 16),                                  \
             kh + (size_t)((k0) + kk) * HD_ + ch * 8);                         \
        int hd = tid >> 2, cv = tid & 3;                                       \
        cp16(saddr(Vt_ + hd * 80 + cv * 16),                                   \
             vth + (size_t)hd * T_ + (k0) + cv * 8);                           \
    }                                                                          \
    const float* rbp_ = rel_bias + ((size_t)bh * T_ + (k0)) * T_ + q0;         \
    _Pragma("unroll")                                                          \
    for (int i = 0; i < 4; i++) {                                              \
        int idx = tid + i * 256;                                               \
        int kk = idx >> 5, qq = (idx & 31) * 4;                                \
        cp16(saddr(&RB_[kk * 132 + qq]), rbp_ + (size_t)kk * T_ + qq);         \
    } } while (0)

    ATT_STAGE_LOAD(0, 0);
    cp16(saddr(&Ms[tid * 4]), g_msk + (size_t)b * T_ + tid * 4);
    CP_COMMIT();
    ATT_STAGE_LOAD(1, 32);
    CP_COMMIT();

    // Q fragments: 4 hd-chunks x 4 regs (half2 words from gmem)
    uint32_t qf[4][4];
    {
        const uint32_t* qa = (const uint32_t*)(qh + (size_t)(q0 + r0) * HD_);
        const uint32_t* qc = (const uint32_t*)(qh + (size_t)(q0 + r1) * HD_);
#pragma unroll
        for (int c = 0; c < 4; c++) {
            qf[c][0] = qa[8 * c + q4];
            qf[c][1] = qc[8 * c + q4];
            qf[c][2] = qa[8 * c + 4 + q4];
            qf[c][3] = qc[8 * c + 4 + q4];
        }
    }
    const float ga0  = g_ga1[(size_t)bh * T_ + q0 + r0];
    const float ga1v = g_ga1[(size_t)bh * T_ + q0 + r1];

    const uint32_t paddr = saddr((char*)Pp + (qb + (lane & 15)) * 80
                                 + ((lane >> 4) & 1) * 16);

    float l0 = 0.f, l1 = 0.f;
    float oacc[8][4];
#pragma unroll
    for (int f = 0; f < 8; f++)
#pragma unroll
        for (int e = 0; e < 4; e++) oacc[f][e] = 0.f;

    for (int kt = 0; kt < 32; kt++) {
        if (kt + 1 < 32) CP_WAIT1(); else CP_WAIT0();
        __syncthreads();
        char*  Ks = smc + (kt & 1) * ATT_STAGE_B;
        char*  Vt = Ks + 4608;
        const float* RB = (const float*)(Ks + 9728);
        const int k0 = kt * 32;

        const uint32_t kbase = saddr(Ks + lane * 144);
        const uint32_t vb0   = saddr(Vt + lane * 80);
        const uint32_t vb1   = saddr(Vt + (32 + lane) * 80);

        // ---- S_log2 init: ga'*rb + mask' ----
        float sacc[4][4];
#pragma unroll
        for (int f = 0; f < 4; f++) {
            int c0 = 8 * f + 2 * q4;
            sacc[f][0] = fmaf(ga0,  RB[c0 * 132 + r0],       Ms[k0 + c0]);
            sacc[f][1] = fmaf(ga0,  RB[(c0 + 1) * 132 + r0], Ms[k0 + c0 + 1]);
            sacc[f][2] = fmaf(ga1v, RB[c0 * 132 + r1],       Ms[k0 + c0]);
            sacc[f][3] = fmaf(ga1v, RB[(c0 + 1) * 132 + r1], Ms[k0 + c0 + 1]);
        }
        // ---- QK: 4 hd-chunks x (2 LDSM + 4 mma) ----
#pragma unroll
        for (int c = 0; c < 4; c++) {
            uint32_t bA[4], bB[4];
            LDSM_X4(bA, kbase + c * 32);
            LDSM_X4(bB, kbase + c * 32 + 16);
#pragma unroll
            for (int f = 0; f < 4; f++) {
                uint32_t bb2[2] = { bA[f], bB[f] };
                mma_f16(sacc[f], qf[c], bb2);
            }
        }

        // ---- static softmax: P = exp2(S); tree l-sum ----
#pragma unroll
        for (int f = 0; f < 4; f++) {
            sacc[f][0] = ex2(sacc[f][0]);
            sacc[f][1] = ex2(sacc[f][1]);
            sacc[f][2] = ex2(sacc[f][2]);
            sacc[f][3] = ex2(sacc[f][3]);
        }
        l0 += ((sacc[0][0] + sacc[0][1]) + (sacc[1][0] + sacc[1][1]))
            + ((sacc[2][0] + sacc[2][1]) + (sacc[3][0] + sacc[3][1]));
        l1 += ((sacc[0][2] + sacc[0][3]) + (sacc[1][2] + sacc[1][3]))
            + ((sacc[2][2] + sacc[2][3]) + (sacc[3][2] + sacc[3][3]));

        // ---- stage P (fp16 half2 words) ----
#pragma unroll
        for (int f = 0; f < 4; f++) {
            __half2 p0 = __floats2half2_rn(sacc[f][0], sacc[f][1]);
            __half2 p1 = __floats2half2_rn(sacc[f][2], sacc[f][3]);
            Pp[r0 * 20 + 4 * f + q4] = *(uint32_t*)&p0;
            Pp[r1 * 20 + 4 * f + q4] = *(uint32_t*)&p1;
        }
        __syncwarp();

        // ---- O += P @ V : 2 k-chunks x (1 pa + 4 V LDSM + 8 mma) ----
#pragma unroll
        for (int cc = 0; cc < 2; cc++) {
            uint32_t pa[4], vA[4], vB[4], vC[4], vD[4];
            LDSM_X4(pa, paddr + cc * 32);
            LDSM_X4(vA, vb0 + cc * 32);
            LDSM_X4(vB, vb0 + cc * 32 + 16);
            LDSM_X4(vC, vb1 + cc * 32);
            LDSM_X4(vD, vb1 + cc * 32 + 16);
#pragma unroll
            for (int f = 0; f < 4; f++) {
                uint32_t bb2[2] = { vA[f], vB[f] };
                mma_f16(oacc[f], pa, bb2);
            }
#pragma unroll
            for (int f = 0; f < 4; f++) {
                uint32_t bb2[2] = { vC[f], vD[f] };
                mma_f16(oacc[4 + f], pa, bb2);
            }
        }
        __syncthreads();
        if (kt + 2 < 32) { ATT_STAGE_LOAD(kt & 1, (kt + 2) * 32); CP_COMMIT(); }
    }

    // ---- reduce l across quad, finalize ----
    l0 += __shfl_xor_sync(0xffffffffu, l0, 1);
    l0 += __shfl_xor_sync(0xffffffffu, l0, 2);
    l1 += __shfl_xor_sync(0xffffffffu, l1, 1);
    l1 += __shfl_xor_sync(0xffffffffu, l1, 2);
    float inv0 = 1.f / l0, inv1 = 1.f / l1;
#pragma unroll
    for (int f = 0; f < 8; f++) {
        int c = 8 * f + 2 * q4;
        size_t i0 = ((size_t)b * T_ + q0 + r0) * D_ + h * HD_ + c;
        size_t i1 = ((size_t)b * T_ + q0 + r1) * D_ + h * HD_ + c;
        float v00 = oacc[f][0] * inv0, v01 = oacc[f][1] * inv0;
        float v10 = oacc[f][2] * inv1, v11 = oacc[f][3] * inv1;
        __nv_bfloat16 h00,l00,h01,l01,h10,l10,h11,l11;
        bfsplit(v00,h00,l00); bfsplit(v01,h01,l01);
        bfsplit(v10,h10,l10); bfsplit(v11,h11,l11);
        *(__nv_bfloat162*)(g_oh + i0) = {h00, h01};
        *(__nv_bfloat162*)(g_ol + i0) = {l00, l01};
        *(__nv_bfloat162*)(g_oh + i1) = {h10, h11};
        *(__nv_bfloat162*)(g_ol + i1) = {l10, l11};
    }
}

// ============================================================
// O-proj GEMM, bf16 3-term with ldmatrix (proven kernel).
// ============================================================
#define OB_STAGE 40960
__global__ __launch_bounds__(256, 2)
void gemm_o3(const __nv_bfloat16* __restrict__ Ah, const __nv_bfloat16* __restrict__ Al,
             const __nv_bfloat16* __restrict__ Bh, const __nv_bfloat16* __restrict__ Bl,
             const float* __restrict__ bias, float* __restrict__ out)
{
    extern __shared__ char smo[];
    const int tid = threadIdx.x;
    const int w = tid >> 5, lane = tid & 31, g = lane >> 2, q4 = lane & 3;
    const int wm = (w & 1) * 64, wn = (w >> 1) * 32;
    const int row0 = blockIdx.x * 128, col0 = blockIdx.y * 128;

    float acc[4][4][4];
#pragma unroll
    for (int i = 0; i < 4; i++)
#pragma unroll
        for (int f = 0; f < 4; f++)
#pragma unroll
            for (int e = 0; e < 4; e++) acc[i][f][e] = 0.f;

    const int lrow = lane & 15;
    const int lchk = (lane >> 4) * 16;

#define O3_STAGE_LOAD(s, k0) do {                                              \
    char* base_ = smo + (s) * OB_STAGE;                                        \
    _Pragma("unroll")                                                          \
    for (int i = 0; i < 2; i++) {                                              \
        int idx = tid + i * 256;                                               \
        int r = idx >> 2, ch = idx & 3;                                        \
        uint32_t so = saddr(base_ + r * 80 + ch * 16);                         \
        cp16(so,         Ah + (size_t)(row0 + r) * D_ + (k0) + ch * 8);        \
        cp16(so + 10240, Al + (size_t)(row0 + r) * D_ + (k0) + ch * 8);        \
        cp16(so + 20480, Bh + (size_t)(col0 + r) * D_ + (k0) + ch * 8);        \
        cp16(so + 30720, Bl + (size_t)(col0 + r) * D_ + (k0) + ch * 8);        \
    } } while (0)

    O3_STAGE_LOAD(0, 0);  CP_COMMIT();
    O3_STAGE_LOAD(1, 32); CP_COMMIT();

    for (int kb = 0; kb < 24; kb++) {
        if (kb + 1 < 24) CP_WAIT1(); else CP_WAIT0();
        __syncthreads();
        char* base = smo + (kb & 1) * OB_STAGE;
#pragma unroll
        for (int ks = 0; ks < 2; ks++) {
            uint32_t ah[4][4], al[4][4];
#pragma unroll
            for (int i = 0; i < 4; i++) {
                uint32_t a = saddr(base + (wm + 16 * i + lrow) * 80 + ks * 32 + lchk);
                LDSM_X4(ah[i], a);
                LDSM_X4(al[i], a + 10240);
            }
            uint32_t bh4[2][4], bl4[2][4];
#pragma unroll
            for (int j = 0; j < 2; j++) {
                uint32_t a = saddr(base + 20480 + (wn + 16 * j + lrow) * 80 + ks * 32 + lchk);
                LDSM_X4(bh4[j], a);
                LDSM_X4(bl4[j], a + 10240);
            }
#pragma unroll
            for (int i = 0; i < 4; i++)
#pragma unroll
                for (int f = 0; f < 4; f++) {
                    uint32_t bhf[2] = { bh4[f >> 1][f & 1], bh4[f >> 1][(f & 1) + 2] };
                    uint32_t blf[2] = { bl4[f >> 1][f & 1], bl4[f >> 1][(f & 1) + 2] };
                    mma_bf16(acc[i][f], ah[i], bhf);
                    mma_bf16(acc[i][f], ah[i], blf);
                    mma_bf16(acc[i][f], al[i], bhf);
                }
        }
        __syncthreads();
        if (kb + 2 < 24) { O3_STAGE_LOAD(kb & 1, (kb + 2) * 32); CP_COMMIT(); }
    }

#pragma unroll
    for (int i = 0; i < 4; i++)
#pragma unroll
        for (int f = 0; f < 4; f++) {
            int col = col0 + wn + 8 * f + 2 * q4;
            float b0 = bias[col], b1 = bias[col + 1];
#pragma unroll
            for (int half = 0; half < 2; half++) {
                int row = row0 + wm + 16 * i + g + 8 * half;
                float2 v;
                v.x = acc[i][f][2 * half + 0] + b0;
                v.y = acc[i][f][2 * half + 1] + b1;
                *(float2*)(out + (size_t)row * D_ + col) = v;
            }
        }
}

// ============================================================
extern "C" void kernel_launch(void* const* d_in, const int* in_sizes, int n_in,
                              void* d_out, int out_size)
{
    const float* x         = (const float*)d_in[0];
    const float* attn_mask = (const float*)d_in[1];
    const float* rel_bias  = (const float*)d_in[2];
    const float* Wq = (const float*)d_in[3];
    const float* bq = (const float*)d_in[4];
    const float* Wk = (const float*)d_in[5];
    const float* bk = (const float*)d_in[6];
    const float* Wv = (const float*)d_in[7];
    const float* bv = (const float*)d_in[8];
    const float* Wo = (const float*)d_in[9];
    const float* bo = (const float*)d_in[10];
    const float* Wg = (const float*)d_in[11];
    const float* bg = (const float*)d_in[12];
    const float* grep_a = (const float*)d_in[13];
    float* out = (float*)d_out;

    __half *x16, *wt16, *q, *k, *v;
    __nv_bfloat16 *woth, *wotl, *oh, *ol;
    float *ga1;
    cudaGetSymbolAddress((void**)&x16,  g_x16);
    cudaGetSymbolAddress((void**)&wt16, g_wt16);
    cudaGetSymbolAddress((void**)&woth, g_woth);
    cudaGetSymbolAddress((void**)&wotl, g_wotl);
    cudaGetSymbolAddress((void**)&q,    g_q);
    cudaGetSymbolAddress((void**)&k,    g_k);
    cudaGetSymbolAddress((void**)&v,    g_v);
    cudaGetSymbolAddress((void**)&oh,   g_oh);
    cudaGetSymbolAddress((void**)&ol,   g_ol);
    cudaGetSymbolAddress((void**)&ga1,  g_ga1);

    cudaFuncSetAttribute(gemm_qkv16,  cudaFuncAttributeMaxDynamicSharedMemorySize, Q16_STAGE * 2);
    cudaFuncSetAttribute(attn_kernel, cudaFuncAttributeMaxDynamicSharedMemorySize, 67584);
    cudaFuncSetAttribute(gemm_o3,     cudaFuncAttributeMaxDynamicSharedMemorySize, OB_STAGE * 2);

    conv_all<<<NXB + 4 * NTB, 256>>>(                                                   // 0
        (const float4*)x, Wq, Wk, Wv, Wo, Wg, bg, x16, wt16, woth, wotl);
    gates_kernel<<<BH_ * T_ / 8, 256>>>(x, grep_a, attn_mask, ga1);                     // 1
    gemm_qkv16<<<dim3(64, 6, 3), 256, Q16_STAGE * 2>>>(                                 // 2
        x16, wt16, bq, bk, bv, q, k, v);
    attn_kernel<<<dim3(T_ / 128, BH_), 256, 67584>>>(rel_bias);                         // 3
    gemm_o3<<<dim3(64, 6), 256, OB_STAGE * 2>>>(oh, ol, woth, wotl, bo, out);           // 4
}

// round 13
// speedup vs baseline: 1.4796x; 1.0922x over previous
#include <cuda_runtime.h>
#include <cuda_fp16.h>
#include <math.h>
#include <stdint.h>

#define B_  8
#define T_  1024
#define D_  768
#define H_  12
#define HD_ 64
#define BH_ (B_*H_)   /* 96 */
#define N_  (B_*T_)   /* 8192 */
#define WSZ_ ((size_t)D_*D_)
#define C_SM  (0.125f * 1.44269504088896340736f)   /* 0.125*log2(e) */
#define K8C   (1.44269504088896340736f)            /* log2(e) */

// ---- scratch (static device globals; no allocation) ----
__device__ __half g_x16[N_*D_];            // x fp16
__device__ __half g_wt16[3][D_*D_];        // Wq/Wk/Wv^T fp16 [n][k]
__device__ __half g_woth[D_*D_];           // Wo^T fp16 hi [n][k]
__device__ __half g_wotl[D_*D_];           // Wo^T fp16 lo
__device__ __half g_q[BH_*T_*HD_];         // fp16 (pre-scaled C_SM), [bh][t][hd]
__device__ __half g_k[BH_*T_*HD_];         // fp16, [bh][t][hd]
__device__ __half g_v[BH_*T_*HD_];         // fp16, TRANSPOSED [bh][hd][t]
__device__ __half g_o16[N_*D_];            // attn out fp16, row-major
__device__ float    g_ga1[BH_*T_];         // log2e * ga1
__device__ float    g_msk[N_];             // log2e * attn_mask
__device__ float    g_wg2[HD_*2];
__device__ float    g_bg2[2];

// ---- helpers ----
__device__ __forceinline__ float ex2(float x) {
    float r;
    asm("ex2.approx.f32 %0, %1;" : "=f"(r) : "f"(x));
    return r;
}
__device__ __forceinline__ void mma_f16(float* d, const uint32_t* a, const uint32_t* b) {
    asm volatile(
        "mma.sync.aligned.m16n8k16.row.col.f32.f16.f16.f32 "
        "{%0,%1,%2,%3}, {%4,%5,%6,%7}, {%8,%9}, {%0,%1,%2,%3};\n"
        : "+f"(d[0]), "+f"(d[1]), "+f"(d[2]), "+f"(d[3])
        : "r"(a[0]), "r"(a[1]), "r"(a[2]), "r"(a[3]), "r"(b[0]), "r"(b[1]));
}
#define LDSM_X4(r, a) \
    asm volatile("ldmatrix.sync.aligned.m8n8.x4.shared.b16 {%0,%1,%2,%3}, [%4];" \
        : "=r"((r)[0]), "=r"((r)[1]), "=r"((r)[2]), "=r"((r)[3]) : "r"(a))

__device__ __forceinline__ uint32_t saddr(const void* p) {
    return (uint32_t)__cvta_generic_to_shared(p);
}
__device__ __forceinline__ void cp16(uint32_t s, const void* g) {
    asm volatile("cp.async.cg.shared.global [%0], [%1], 16;\n" :: "r"(s), "l"(g));
}
#define CP_COMMIT() asm volatile("cp.async.commit_group;\n")
#define CP_WAIT2()  asm volatile("cp.async.wait_group 2;\n")
#define CP_WAIT1()  asm volatile("cp.async.wait_group 1;\n")
#define CP_WAIT0()  asm volatile("cp.async.wait_group 0;\n")

// ============================================================
// conv_all: x -> fp16 ; Wq/Wk/Wv -> W^T fp16 ; Wo -> W^T fp16 hi/lo;
// block 0: Wg row-sums.
// ============================================================
#define NXB 6144
#define NTB 576
__global__ __launch_bounds__(256)
void conv_all(const float4* __restrict__ x,
              const float* __restrict__ Wq, const float* __restrict__ Wk,
              const float* __restrict__ Wv, const float* __restrict__ Wo,
              const float* __restrict__ Wg, const float* __restrict__ bg,
              __half* __restrict__ x16, __half* __restrict__ wt16,
              __half* __restrict__ woth, __half* __restrict__ wotl)
{
    __shared__ float tile[32][33];
    const int bid = blockIdx.x, tid = threadIdx.x;

    if (bid == 0 && tid < 64) {
        int d = tid;
        const float* wg = Wg + d * 8;
        g_wg2[d * 2 + 0] = wg[0] + wg[1] + wg[2] + wg[3];
        g_wg2[d * 2 + 1] = wg[4] + wg[5] + wg[6] + wg[7];
        if (d == 0) {
            g_bg2[0] = bg[0] + bg[1] + bg[2] + bg[3];
            g_bg2[1] = bg[4] + bg[5] + bg[6] + bg[7];
        }
    }

    if (bid < NXB) {
        int i = bid * 256 + tid;
        float4 v = x[i];
        *(__half2*)(x16 + (size_t)i * 4)     = __floats2half2_rn(v.x, v.y);
        *(__half2*)(x16 + (size_t)i * 4 + 2) = __floats2half2_rn(v.z, v.w);
    } else {
        int r = bid - NXB;
        int z = r / NTB;                 // 0..3
        int bx = r % NTB;
        int n0 = (bx % 24) * 32, k0 = (bx / 24) * 32;
        const float* W = (z == 0) ? Wq : (z == 1) ? Wk : (z == 2) ? Wv : Wo;
        int tx = tid & 31, ty0 = tid >> 5;
#pragma unroll
        for (int j = 0; j < 4; j++)
            tile[ty0 + 8 * j][tx] = W[(size_t)(k0 + ty0 + 8 * j) * D_ + n0 + tx];
        __syncthreads();
#pragma unroll
        for (int j = 0; j < 4; j++) {
            int ty = ty0 + 8 * j;
            float f = tile[tx][ty];
            size_t o = (size_t)(n0 + ty) * D_ + k0 + tx;
            if (z < 3) {
                wt16[(size_t)z * WSZ_ + o] = __float2half(f);
            } else {
                __half h = __float2half(f);
                woth[o] = h;
                wotl[o] = __float2half(f - __half2float(h));
            }
        }
    }
}

// ============================================================
// Gates: emits log2e*ga1 ; also pre-scales the mask.
// ============================================================
__global__ __launch_bounds__(256)
void gates_kernel(const float* __restrict__ x, const float* __restrict__ grep_a,
                  const float* __restrict__ attn_mask, float* __restrict__ ga1)
{
    int gidx = blockIdx.x * 256 + threadIdx.x;
    if (gidx < N_) g_msk[gidx] = K8C * attn_mask[gidx];

    int w    = blockIdx.x * 8 + (threadIdx.x >> 5);
    int lane = threadIdx.x & 31;
    int bh = w >> 10, t = w & 1023;
    int b = bh / H_, h = bh % H_;
    const float* xp = x + ((size_t)b * T_ + t) * D_ + h * HD_;

    float s0 = 0.f, s1 = 0.f;
#pragma unroll
    for (int d = lane; d < HD_; d += 32) {
        float xv = xp[d];
        s0 += xv * g_wg2[d * 2 + 0];
        s1 += xv * g_wg2[d * 2 + 1];
    }
#pragma unroll
    for (int off = 16; off > 0; off >>= 1) {
        s0 += __shfl_xor_sync(0xffffffffu, s0, off);
        s1 += __shfl_xor_sync(0xffffffffu, s1, off);
    }
    if (lane == 0) {
        s0 += g_bg2[0];
        s1 += g_bg2[1];
        float ga = 1.f / (1.f + expf(-s0));
        float gb = 1.f / (1.f + expf(-s1));
        ga1[w] = K8C * (ga * (gb * grep_a[h] - 1.f) + 2.f);
    }
}

// ============================================================
// QKV GEMM, fp16 1-term, ldmatrix (proven R12 kernel).
// ============================================================
#define Q16_STAGE 20480
__global__ __launch_bounds__(256, 2)
void gemm_qkv16(const __half* __restrict__ A, const __half* __restrict__ WT,
                const float* __restrict__ bb0, const float* __restrict__ bb1,
                const float* __restrict__ bb2,
                __half* __restrict__ o0, __half* __restrict__ o1,
                __half* __restrict__ o2)
{
    extern __shared__ char smq[];
    const int z = blockIdx.z;
    const __half* B = WT + (size_t)z * WSZ_;
    const float* bias = (z == 0) ? bb0 : (z == 1) ? bb1 : bb2;
    __half* out       = (z == 0) ? o0 : (z == 1) ? o1 : o2;
    const float oscale = (z == 0) ? C_SM : 1.f;

    const int tid = threadIdx.x;
    const int w = tid >> 5, lane = tid & 31, g = lane >> 2, q4 = lane & 3;
    const int wm = (w & 1) * 64, wn = (w >> 1) * 32;
    const int row0 = blockIdx.x * 128, col0 = blockIdx.y * 128;

    float acc[4][4][4];
#pragma unroll
    for (int i = 0; i < 4; i++)
#pragma unroll
        for (int f = 0; f < 4; f++)
#pragma unroll
            for (int e = 0; e < 4; e++) acc[i][f][e] = 0.f;

    const int lrow = lane & 15;
    const int lchk = (lane >> 4) * 16;

#define Q16_STAGE_LOAD(s, k0) do {                                             \
    char* base_ = smq + (s) * Q16_STAGE;                                       \
    _Pragma("unroll")                                                          \
    for (int i = 0; i < 2; i++) {                                              \
        int idx = tid + i * 256;                                               \
        int r = idx >> 2, ch = idx & 3;                                        \
        uint32_t so = saddr(base_ + r * 80 + ch * 16);                         \
        cp16(so,         A + (size_t)(row0 + r) * D_ + (k0) + ch * 8);         \
        cp16(so + 10240, B + (size_t)(col0 + r) * D_ + (k0) + ch * 8);         \
    } } while (0)

    Q16_STAGE_LOAD(0, 0);  CP_COMMIT();
    Q16_STAGE_LOAD(1, 32); CP_COMMIT();

    for (int kb = 0; kb < 24; kb++) {
        if (kb + 1 < 24) CP_WAIT1(); else CP_WAIT0();
        __syncthreads();
        char* base = smq + (kb & 1) * Q16_STAGE;
#pragma unroll
        for (int ks = 0; ks < 2; ks++) {
            uint32_t ah[4][4], bh4[2][4];
#pragma unroll
            for (int i = 0; i < 4; i++)
                LDSM_X4(ah[i], saddr(base + (wm + 16 * i + lrow) * 80 + ks * 32 + lchk));
#pragma unroll
            for (int j = 0; j < 2; j++)
                LDSM_X4(bh4[j], saddr(base + 10240 + (wn + 16 * j + lrow) * 80 + ks * 32 + lchk));
#pragma unroll
            for (int i = 0; i < 4; i++)
#pragma unroll
                for (int f = 0; f < 4; f++) {
                    uint32_t bf2[2] = { bh4[f >> 1][f & 1], bh4[f >> 1][(f & 1) + 2] };
                    mma_f16(acc[i][f], ah[i], bf2);
                }
        }
        __syncthreads();
        if (kb + 2 < 24) { Q16_STAGE_LOAD(kb & 1, (kb + 2) * 32); CP_COMMIT(); }
    }

#pragma unroll
    for (int i = 0; i < 4; i++)
#pragma unroll
        for (int f = 0; f < 4; f++) {
            int col = col0 + wn + 8 * f + 2 * q4;
            float b0 = bias[col], b1 = bias[col + 1];
            int hh = col >> 6, hd = col & 63;
#pragma unroll
            for (int half = 0; half < 2; half++) {
                int row = row0 + wm + 16 * i + g + 8 * half;
                int bb = row >> 10, tt = row & 1023;
                float v0 = (acc[i][f][2 * half + 0] + b0) * oscale;
                float v1 = (acc[i][f][2 * half + 1] + b1) * oscale;
                if (z == 2) {
                    __half* dst = out + (size_t)(bb * H_ + hh) * HD_ * T_ + tt;
                    dst[(size_t)hd * T_]       = __float2half(v0);
                    dst[(size_t)(hd + 1) * T_] = __float2half(v1);
                } else {
                    *(__half2*)(out + ((size_t)(bb * H_ + hh) * T_ + tt) * HD_ + hd)
                        = __floats2half2_rn(v0, v1);
                }
            }
        }
}

// ============================================================
// Flash attention: fp16 K/V/P/Q, rel_bias via direct LDG (no smem),
// 3-stage K/V cp.async ring.
// stage: Ks 32x144B (4608) + Vt 64x80B (5120) = 9728 B
//  x3 stages = 29184 ; P 128x80B = 10240 ; Ms 4096 => 43520 B
// ============================================================
#define ATT_STG_B 9728
__global__ __launch_bounds__(256, 2)
void attn_kernel(const float* __restrict__ rel_bias)
{
    extern __shared__ char smc[];
    uint32_t* Pp = (uint32_t*)(smc + 3 * ATT_STG_B);
    float*    Ms = (float*)(smc + 3 * ATT_STG_B + 10240);

    const int tid  = threadIdx.x;
    const int w    = tid >> 5;
    const int lane = tid & 31;
    const int g    = lane >> 2;
    const int q4   = lane & 3;
    const int qb   = 16 * w;
    const int q0   = blockIdx.x * 128;
    const int bh   = blockIdx.y;
    const int b    = bh / H_, h = bh % H_;

    const __half* qh  = g_q + (size_t)bh * T_ * HD_;
    const __half* kh  = g_k + (size_t)bh * T_ * HD_;
    const __half* vth = g_v + (size_t)bh * HD_ * T_;   // [hd][t]

    const int r0 = qb + g;
    const int r1 = qb + g + 8;

#define ATT_STAGE_LOAD(s, k0) do {                                             \
    char* Ks_ = smc + (s) * ATT_STG_B;                                         \
    char* Vt_ = Ks_ + 4608;                                                    \
    int kk = tid >> 3, ch = tid & 7;                                           \
    cp16(saddr(Ks_ + kk * 144 + ch * 16),                                      \
         kh + (size_t)((k0) + kk) * HD_ + ch * 8);                             \
    int hd = tid >> 2, cv = tid & 3;                                           \
    cp16(saddr(Vt_ + hd * 80 + cv * 16),                                       \
         vth + (size_t)hd * T_ + (k0) + cv * 8);                               \
    } while (0)

    ATT_STAGE_LOAD(0, 0);
    cp16(saddr(&Ms[tid * 4]), g_msk + (size_t)b * T_ + tid * 4);
    CP_COMMIT();
    ATT_STAGE_LOAD(1, 32);
    CP_COMMIT();
    ATT_STAGE_LOAD(2, 64);
    CP_COMMIT();

    // Q fragments
    uint32_t qf[4][4];
    {
        const uint32_t* qa = (const uint32_t*)(qh + (size_t)(q0 + r0) * HD_);
        const uint32_t* qc = (const uint32_t*)(qh + (size_t)(q0 + r1) * HD_);
#pragma unroll
        for (int c = 0; c < 4; c++) {
            qf[c][0] = qa[8 * c + q4];
            qf[c][1] = qc[8 * c + q4];
            qf[c][2] = qa[8 * c + 4 + q4];
            qf[c][3] = qc[8 * c + 4 + q4];
        }
    }
    const float ga0  = g_ga1[(size_t)bh * T_ + q0 + r0];
    const float ga1v = g_ga1[(size_t)bh * T_ + q0 + r1];

    // per-thread rel_bias base: rows (k) offset 2*q4, cols (q) r0 / r1
    const float* rbt = rel_bias + ((size_t)bh * T_ + 2 * q4) * T_ + q0;

    const uint32_t paddr = saddr((char*)Pp + (qb + (lane & 15)) * 80
                                 + ((lane >> 4) & 1) * 16);

    float l0 = 0.f, l1 = 0.f;
    float oacc[8][4];
#pragma unroll
    for (int f = 0; f < 8; f++)
#pragma unroll
        for (int e = 0; e < 4; e++) oacc[f][e] = 0.f;

    for (int kt = 0; kt < 32; kt++) {
        const int k0 = kt * 32;

        // ---- issue rel_bias LDGs (consumed after QK mmas) ----
        float rbv[4][4];
#pragma unroll
        for (int f = 0; f < 4; f++) {
            const float* p = rbt + (size_t)(k0 + 8 * f) * T_;
            rbv[f][0] = __ldg(p + r0);
            rbv[f][1] = __ldg(p + T_ + r0);
            rbv[f][2] = __ldg(p + r1);
            rbv[f][3] = __ldg(p + T_ + r1);
        }

        if (kt + 2 < 32) CP_WAIT2(); else CP_WAIT0();
        __syncthreads();
        const int slot = kt % 3;
        char* Ks = smc + slot * ATT_STG_B;
        char* Vt = Ks + 4608;
        const uint32_t kbase = saddr(Ks + lane * 144);
        const uint32_t vb0   = saddr(Vt + lane * 80);
        const uint32_t vb1   = saddr(Vt + (32 + lane) * 80);

        // ---- QK into zero-init sacc ----
        float sacc[4][4];
#pragma unroll
        for (int f = 0; f < 4; f++)
#pragma unroll
            for (int e = 0; e < 4; e++) sacc[f][e] = 0.f;
#pragma unroll
        for (int c = 0; c < 4; c++) {
            uint32_t bA[4], bB[4];
            LDSM_X4(bA, kbase + c * 32);
            LDSM_X4(bB, kbase + c * 32 + 16);
#pragma unroll
            for (int f = 0; f < 4; f++) {
                uint32_t bb2[2] = { bA[f], bB[f] };
                mma_f16(sacc[f], qf[c], bb2);
            }
        }

        // ---- P = exp2(qk + ga'*rb + msk') ; tree l-sum ----
#pragma unroll
        for (int f = 0; f < 4; f++) {
            int c0 = 8 * f + 2 * q4;
            sacc[f][0] = ex2(sacc[f][0] + fmaf(ga0,  rbv[f][0], Ms[k0 + c0]));
            sacc[f][1] = ex2(sacc[f][1] + fmaf(ga0,  rbv[f][1], Ms[k0 + c0 + 1]));
            sacc[f][2] = ex2(sacc[f][2] + fmaf(ga1v, rbv[f][2], Ms[k0 + c0]));
            sacc[f][3] = ex2(sacc[f][3] + fmaf(ga1v, rbv[f][3], Ms[k0 + c0 + 1]));
        }
        l0 += ((sacc[0][0] + sacc[0][1]) + (sacc[1][0] + sacc[1][1]))
            + ((sacc[2][0] + sacc[2][1]) + (sacc[3][0] + sacc[3][1]));
        l1 += ((sacc[0][2] + sacc[0][3]) + (sacc[1][2] + sacc[1][3]))
            + ((sacc[2][2] + sacc[2][3]) + (sacc[3][2] + sacc[3][3]));

        // ---- stage P (fp16 half2 words) ----
#pragma unroll
        for (int f = 0; f < 4; f++) {
            __half2 p0 = __floats2half2_rn(sacc[f][0], sacc[f][1]);
            __half2 p1 = __floats2half2_rn(sacc[f][2], sacc[f][3]);
            Pp[r0 * 20 + 4 * f + q4] = *(uint32_t*)&p0;
            Pp[r1 * 20 + 4 * f + q4] = *(uint32_t*)&p1;
        }
        __syncwarp();

        // ---- O += P @ V ----
#pragma unroll
        for (int cc = 0; cc < 2; cc++) {
            uint32_t pa[4], vA[4], vB[4], vC[4], vD[4];
            LDSM_X4(pa, paddr + cc * 32);
            LDSM_X4(vA, vb0 + cc * 32);
            LDSM_X4(vB, vb0 + cc * 32 + 16);
            LDSM_X4(vC, vb1 + cc * 32);
            LDSM_X4(vD, vb1 + cc * 32 + 16);
#pragma unroll
            for (int f = 0; f < 4; f++) {
                uint32_t bb2[2] = { vA[f], vB[f] };
                mma_f16(oacc[f], pa, bb2);
            }
#pragma unroll
            for (int f = 0; f < 4; f++) {
                uint32_t bb2[2] = { vC[f], vD[f] };
                mma_f16(oacc[4 + f], pa, bb2);
            }
        }
        __syncthreads();
        if (kt + 3 < 32) { ATT_STAGE_LOAD(slot, (kt + 3) * 32); CP_COMMIT(); }
    }

    // ---- reduce l across quad, finalize: fp16 out ----
    l0 += __shfl_xor_sync(0xffffffffu, l0, 1);
    l0 += __shfl_xor_sync(0xffffffffu, l0, 2);
    l1 += __shfl_xor_sync(0xffffffffu, l1, 1);
    l1 += __shfl_xor_sync(0xffffffffu, l1, 2);
    float inv0 = 1.f / l0, inv1 = 1.f / l1;
#pragma unroll
    for (int f = 0; f < 8; f++) {
        int c = 8 * f + 2 * q4;
        size_t i0 = ((size_t)b * T_ + q0 + r0) * D_ + h * HD_ + c;
        size_t i1 = ((size_t)b * T_ + q0 + r1) * D_ + h * HD_ + c;
        *(__half2*)(g_o16 + i0) = __floats2half2_rn(oacc[f][0] * inv0, oacc[f][1] * inv0);
        *(__half2*)(g_o16 + i1) = __floats2half2_rn(oacc[f][2] * inv1, oacc[f][3] * inv1);
    }
}

// ============================================================
// O-proj GEMM, fp16 2-term (A.Bh + A.Bl) with ldmatrix.
// stage: A 10240 + Bh 10240 + Bl 10240 = 30720 B ; x2 stages.
// ============================================================
#define O2_STAGE 30720
__global__ __launch_bounds__(256, 2)
void gemm_o2(const __half* __restrict__ A,
             const __half* __restrict__ Bh, const __half* __restrict__ Bl,
             const float* __restrict__ bias, float* __restrict__ out)
{
    extern __shared__ char smo[];
    const int tid = threadIdx.x;
    const int w = tid >> 5, lane = tid & 31, g = lane >> 2, q4 = lane & 3;
    const int wm = (w & 1) * 64, wn = (w >> 1) * 32;
    const int row0 = blockIdx.x * 128, col0 = blockIdx.y * 128;

    float acc[4][4][4];
#pragma unroll
    for (int i = 0; i < 4; i++)
#pragma unroll
        for (int f = 0; f < 4; f++)
#pragma unroll
            for (int e = 0; e < 4; e++) acc[i][f][e] = 0.f;

    const int lrow = lane & 15;
    const int lchk = (lane >> 4) * 16;

#define O2_STAGE_LOAD(s, k0) do {                                              \
    char* base_ = smo + (s) * O2_STAGE;                                        \
    _Pragma("unroll")                                                          \
    for (int i = 0; i < 2; i++) {                                              \
        int idx = tid + i * 256;                                               \
        int r = idx >> 2, ch = idx & 3;                                        \
        uint32_t so = saddr(base_ + r * 80 + ch * 16);                         \
        cp16(so,         A  + (size_t)(row0 + r) * D_ + (k0) + ch * 8);        \
        cp16(so + 10240, Bh + (size_t)(col0 + r) * D_ + (k0) + ch * 8);        \
        cp16(so + 20480, Bl + (size_t)(col0 + r) * D_ + (k0) + ch * 8);        \
    } } while (0)

    O2_STAGE_LOAD(0, 0);  CP_COMMIT();
    O2_STAGE_LOAD(1, 32); CP_COMMIT();

    for (int kb = 0; kb < 24; kb++) {
        if (kb + 1 < 24) CP_WAIT1(); else CP_WAIT0();
        __syncthreads();
        char* base = smo + (kb & 1) * O2_STAGE;
#pragma unroll
        for (int ks = 0; ks < 2; ks++) {
            uint32_t ah[4][4];
#pragma unroll
            for (int i = 0; i < 4; i++)
                LDSM_X4(ah[i], saddr(base + (wm + 16 * i + lrow) * 80 + ks * 32 + lchk));
            uint32_t bh4[2][4], bl4[2][4];
#pragma unroll
            for (int j = 0; j < 2; j++) {
                uint32_t a = saddr(base + 10240 + (wn + 16 * j + lrow) * 80 + ks * 32 + lchk);
                LDSM_X4(bh4[j], a);
                LDSM_X4(bl4[j], a + 10240);
            }
#pragma unroll
            for (int i = 0; i < 4; i++)
#pragma unroll
                for (int f = 0; f < 4; f++) {
                    uint32_t bhf[2] = { bh4[f >> 1][f & 1], bh4[f >> 1][(f & 1) + 2] };
                    uint32_t blf[2] = { bl4[f >> 1][f & 1], bl4[f >> 1][(f & 1) + 2] };
                    mma_f16(acc[i][f], ah[i], bhf);
                    mma_f16(acc[i][f], ah[i], blf);
                }
        }
        __syncthreads();
        if (kb + 2 < 24) { O2_STAGE_LOAD(kb & 1, (kb + 2) * 32); CP_COMMIT(); }
    }

#pragma unroll
    for (int i = 0; i < 4; i++)
#pragma unroll
        for (int f = 0; f < 4; f++) {
            int col = col0 + wn + 8 * f + 2 * q4;
            float b0 = bias[col], b1 = bias[col + 1];
#pragma unroll
            for (int half = 0; half < 2; half++) {
                int row = row0 + wm + 16 * i + g + 8 * half;
                float2 v;
                v.x = acc[i][f][2 * half + 0] + b0;
                v.y = acc[i][f][2 * half + 1] + b1;
                *(float2*)(out + (size_t)row * D_ + col) = v;
            }
        }
}

// ============================================================
extern "C" void kernel_launch(void* const* d_in, const int* in_sizes, int n_in,
                              void* d_out, int out_size)
{
    const float* x         = (const float*)d_in[0];
    const float* attn_mask = (const float*)d_in[1];
    const float* rel_bias  = (const float*)d_in[2];
    const float* Wq = (const float*)d_in[3];
    const float* bq = (const float*)d_in[4];
    const float* Wk = (const float*)d_in[5];
    const float* bk = (const float*)d_in[6];
    const float* Wv = (const float*)d_in[7];
    const float* bv = (const float*)d_in[8];
    const float* Wo = (const float*)d_in[9];
    const float* bo = (const float*)d_in[10];
    const float* Wg = (const float*)d_in[11];
    const float* bg = (const float*)d_in[12];
    const float* grep_a = (const float*)d_in[13];
    float* out = (float*)d_out;

    __half *x16, *wt16, *woth, *wotl, *q, *k, *v, *o16;
    float *ga1;
    cudaGetSymbolAddress((void**)&x16,  g_x16);
    cudaGetSymbolAddress((void**)&wt16, g_wt16);
    cudaGetSymbolAddress((void**)&woth, g_woth);
    cudaGetSymbolAddress((void**)&wotl, g_wotl);
    cudaGetSymbolAddress((void**)&q,    g_q);
    cudaGetSymbolAddress((void**)&k,    g_k);
    cudaGetSymbolAddress((void**)&v,    g_v);
    cudaGetSymbolAddress((void**)&o16,  g_o16);
    cudaGetSymbolAddress((void**)&ga1,  g_ga1);

    cudaFuncSetAttribute(gemm_qkv16,  cudaFuncAttributeMaxDynamicSharedMemorySize, Q16_STAGE * 2);
    cudaFuncSetAttribute(attn_kernel, cudaFuncAttributeMaxDynamicSharedMemorySize, 43520);
    cudaFuncSetAttribute(gemm_o2,     cudaFuncAttributeMaxDynamicSharedMemorySize, O2_STAGE * 2);

    conv_all<<<NXB + 4 * NTB, 256>>>(                                                   // 0
        (const float4*)x, Wq, Wk, Wv, Wo, Wg, bg, x16, wt16, woth, wotl);
    gates_kernel<<<BH_ * T_ / 8, 256>>>(x, grep_a, attn_mask, ga1);                     // 1
    gemm_qkv16<<<dim3(64, 6, 3), 256, Q16_STAGE * 2>>>(                                 // 2
        x16, wt16, bq, bk, bv, q, k, v);
    attn_kernel<<<dim3(T_ / 128, BH_), 256, 43520>>>(rel_bias);                         // 3
    gemm_o2<<<dim3(64, 6), 256, O2_STAGE * 2>>>(o16, woth, wotl, bo, out);              // 4
}

// round 14
// speedup vs baseline: 1.5355x; 1.0378x over previous
#include <cuda_runtime.h>
#include <cuda_fp16.h>
#include <math.h>
#include <stdint.h>

#define B_  8
#define T_  1024
#define D_  768
#define H_  12
#define HD_ 64
#define BH_ (B_*H_)   /* 96 */
#define N_  (B_*T_)   /* 8192 */
#define WSZ_ ((size_t)D_*D_)
#define C_SM  (0.125f * 1.44269504088896340736f)   /* 0.125*log2(e) */
#define K8C   (1.44269504088896340736f)            /* log2(e) */

// ---- scratch (static device globals; no allocation) ----
__device__ __half g_x16[N_*D_];            // x fp16
__device__ __half g_wt16[3][D_*D_];        // Wq/Wk/Wv^T fp16 [n][k]
__device__ __half g_woth[D_*D_];           // Wo^T fp16 hi [n][k]
__device__ __half g_wotl[D_*D_];           // Wo^T fp16 lo
__device__ __half g_q[BH_*T_*HD_];         // fp16 (pre-scaled C_SM), [bh][t][hd]
__device__ __half g_k[BH_*T_*HD_];         // fp16, [bh][t][hd]
__device__ __half g_v[BH_*T_*HD_];         // fp16, TRANSPOSED [bh][hd][t]
__device__ __half g_o16[N_*D_];            // attn out fp16, row-major
__device__ float    g_ga1[BH_*T_];         // log2e * ga1
__device__ float    g_msk[N_];             // log2e * attn_mask
__device__ float    g_wg2[HD_*2];
__device__ float    g_bg2[2];

// ---- helpers ----
__device__ __forceinline__ float ex2(float x) {
    float r;
    asm("ex2.approx.f32 %0, %1;" : "=f"(r) : "f"(x));
    return r;
}
__device__ __forceinline__ void mma_f16(float* d, const uint32_t* a, const uint32_t* b) {
    asm volatile(
        "mma.sync.aligned.m16n8k16.row.col.f32.f16.f16.f32 "
        "{%0,%1,%2,%3}, {%4,%5,%6,%7}, {%8,%9}, {%0,%1,%2,%3};\n"
        : "+f"(d[0]), "+f"(d[1]), "+f"(d[2]), "+f"(d[3])
        : "r"(a[0]), "r"(a[1]), "r"(a[2]), "r"(a[3]), "r"(b[0]), "r"(b[1]));
}
#define LDSM_X4(r, a) \
    asm volatile("ldmatrix.sync.aligned.m8n8.x4.shared.b16 {%0,%1,%2,%3}, [%4];" \
        : "=r"((r)[0]), "=r"((r)[1]), "=r"((r)[2]), "=r"((r)[3]) : "r"(a))

__device__ __forceinline__ uint32_t saddr(const void* p) {
    return (uint32_t)__cvta_generic_to_shared(p);
}
__device__ __forceinline__ void cp16(uint32_t s, const void* g) {
    asm volatile("cp.async.cg.shared.global [%0], [%1], 16;\n" :: "r"(s), "l"(g));
}
#define CP_COMMIT() asm volatile("cp.async.commit_group;\n")
#define CP_WAIT2()  asm volatile("cp.async.wait_group 2;\n")
#define CP_WAIT1()  asm volatile("cp.async.wait_group 1;\n")
#define CP_WAIT0()  asm volatile("cp.async.wait_group 0;\n")

__device__ __forceinline__ uint32_t h2u(__half2 h) { return *(uint32_t*)&h; }

// ============================================================
// conv_all: x -> fp16 ; Wq/Wk/Wv -> W^T fp16 ; Wo -> W^T fp16 hi/lo;
// block 0: Wg row-sums.
// ============================================================
#define NXB 6144
#define NTB 576
__global__ __launch_bounds__(256)
void conv_all(const float4* __restrict__ x,
              const float* __restrict__ Wq, const float* __restrict__ Wk,
              const float* __restrict__ Wv, const float* __restrict__ Wo,
              const float* __restrict__ Wg, const float* __restrict__ bg,
              __half* __restrict__ x16, __half* __restrict__ wt16,
              __half* __restrict__ woth, __half* __restrict__ wotl)
{
    __shared__ float tile[32][33];
    const int bid = blockIdx.x, tid = threadIdx.x;

    if (bid == 0 && tid < 64) {
        int d = tid;
        const float* wg = Wg + d * 8;
        g_wg2[d * 2 + 0] = wg[0] + wg[1] + wg[2] + wg[3];
        g_wg2[d * 2 + 1] = wg[4] + wg[5] + wg[6] + wg[7];
        if (d == 0) {
            g_bg2[0] = bg[0] + bg[1] + bg[2] + bg[3];
            g_bg2[1] = bg[4] + bg[5] + bg[6] + bg[7];
        }
    }

    if (bid < NXB) {
        int i = bid * 256 + tid;
        float4 v = x[i];
        *(__half2*)(x16 + (size_t)i * 4)     = __floats2half2_rn(v.x, v.y);
        *(__half2*)(x16 + (size_t)i * 4 + 2) = __floats2half2_rn(v.z, v.w);
    } else {
        int r = bid - NXB;
        int z = r / NTB;                 // 0..3
        int bx = r % NTB;
        int n0 = (bx % 24) * 32, k0 = (bx / 24) * 32;
        const float* W = (z == 0) ? Wq : (z == 1) ? Wk : (z == 2) ? Wv : Wo;
        int tx = tid & 31, ty0 = tid >> 5;
#pragma unroll
        for (int j = 0; j < 4; j++)
            tile[ty0 + 8 * j][tx] = W[(size_t)(k0 + ty0 + 8 * j) * D_ + n0 + tx];
        __syncthreads();
#pragma unroll
        for (int j = 0; j < 4; j++) {
            int ty = ty0 + 8 * j;
            float f = tile[tx][ty];
            size_t o = (size_t)(n0 + ty) * D_ + k0 + tx;
            if (z < 3) {
                wt16[(size_t)z * WSZ_ + o] = __float2half(f);
            } else {
                __half h = __float2half(f);
                woth[o] = h;
                wotl[o] = __float2half(f - __half2float(h));
            }
        }
    }
}

// ============================================================
// Gates: emits log2e*ga1 ; also pre-scales the mask.
// ============================================================
__global__ __launch_bounds__(256)
void gates_kernel(const float* __restrict__ x, const float* __restrict__ grep_a,
                  const float* __restrict__ attn_mask, float* __restrict__ ga1)
{
    int gidx = blockIdx.x * 256 + threadIdx.x;
    if (gidx < N_) g_msk[gidx] = K8C * attn_mask[gidx];

    int w    = blockIdx.x * 8 + (threadIdx.x >> 5);
    int lane = threadIdx.x & 31;
    int bh = w >> 10, t = w & 1023;
    int b = bh / H_, h = bh % H_;
    const float* xp = x + ((size_t)b * T_ + t) * D_ + h * HD_;

    float s0 = 0.f, s1 = 0.f;
#pragma unroll
    for (int d = lane; d < HD_; d += 32) {
        float xv = xp[d];
        s0 += xv * g_wg2[d * 2 + 0];
        s1 += xv * g_wg2[d * 2 + 1];
    }
#pragma unroll
    for (int off = 16; off > 0; off >>= 1) {
        s0 += __shfl_xor_sync(0xffffffffu, s0, off);
        s1 += __shfl_xor_sync(0xffffffffu, s1, off);
    }
    if (lane == 0) {
        s0 += g_bg2[0];
        s1 += g_bg2[1];
        float ga = 1.f / (1.f + expf(-s0));
        float gb = 1.f / (1.f + expf(-s1));
        ga1[w] = K8C * (ga * (gb * grep_a[h] - 1.f) + 2.f);
    }
}

// ============================================================
// QKV GEMM, fp16 1-term, ldmatrix (proven kernel).
// ============================================================
#define Q16_STAGE 20480
__global__ __launch_bounds__(256, 2)
void gemm_qkv16(const __half* __restrict__ A, const __half* __restrict__ WT,
                const float* __restrict__ bb0, const float* __restrict__ bb1,
                const float* __restrict__ bb2,
                __half* __restrict__ o0, __half* __restrict__ o1,
                __half* __restrict__ o2)
{
    extern __shared__ char smq[];
    const int z = blockIdx.z;
    const __half* B = WT + (size_t)z * WSZ_;
    const float* bias = (z == 0) ? bb0 : (z == 1) ? bb1 : bb2;
    __half* out       = (z == 0) ? o0 : (z == 1) ? o1 : o2;
    const float oscale = (z == 0) ? C_SM : 1.f;

    const int tid = threadIdx.x;
    const int w = tid >> 5, lane = tid & 31, g = lane >> 2, q4 = lane & 3;
    const int wm = (w & 1) * 64, wn = (w >> 1) * 32;
    const int row0 = blockIdx.x * 128, col0 = blockIdx.y * 128;

    float acc[4][4][4];
#pragma unroll
    for (int i = 0; i < 4; i++)
#pragma unroll
        for (int f = 0; f < 4; f++)
#pragma unroll
            for (int e = 0; e < 4; e++) acc[i][f][e] = 0.f;

    const int lrow = lane & 15;
    const int lchk = (lane >> 4) * 16;

#define Q16_STAGE_LOAD(s, k0) do {                                             \
    char* base_ = smq + (s) * Q16_STAGE;                                       \
    _Pragma("unroll")                                                          \
    for (int i = 0; i < 2; i++) {                                              \
        int idx = tid + i * 256;                                               \
        int r = idx >> 2, ch = idx & 3;                                        \
        uint32_t so = saddr(base_ + r * 80 + ch * 16);                         \
        cp16(so,         A + (size_t)(row0 + r) * D_ + (k0) + ch * 8);         \
        cp16(so + 10240, B + (size_t)(col0 + r) * D_ + (k0) + ch * 8);         \
    } } while (0)

    Q16_STAGE_LOAD(0, 0);  CP_COMMIT();
    Q16_STAGE_LOAD(1, 32); CP_COMMIT();

    for (int kb = 0; kb < 24; kb++) {
        if (kb + 1 < 24) CP_WAIT1(); else CP_WAIT0();
        __syncthreads();
        char* base = smq + (kb & 1) * Q16_STAGE;
#pragma unroll
        for (int ks = 0; ks < 2; ks++) {
            uint32_t ah[4][4], bh4[2][4];
#pragma unroll
            for (int i = 0; i < 4; i++)
                LDSM_X4(ah[i], saddr(base + (wm + 16 * i + lrow) * 80 + ks * 32 + lchk));
#pragma unroll
            for (int j = 0; j < 2; j++)
                LDSM_X4(bh4[j], saddr(base + 10240 + (wn + 16 * j + lrow) * 80 + ks * 32 + lchk));
#pragma unroll
            for (int i = 0; i < 4; i++)
#pragma unroll
                for (int f = 0; f < 4; f++) {
                    uint32_t bf2[2] = { bh4[f >> 1][f & 1], bh4[f >> 1][(f & 1) + 2] };
                    mma_f16(acc[i][f], ah[i], bf2);
                }
        }
        __syncthreads();
        if (kb + 2 < 24) { Q16_STAGE_LOAD(kb & 1, (kb + 2) * 32); CP_COMMIT(); }
    }

#pragma unroll
    for (int i = 0; i < 4; i++)
#pragma unroll
        for (int f = 0; f < 4; f++) {
            int col = col0 + wn + 8 * f + 2 * q4;
            float b0 = bias[col], b1 = bias[col + 1];
            int hh = col >> 6, hd = col & 63;
#pragma unroll
            for (int half = 0; half < 2; half++) {
                int row = row0 + wm + 16 * i + g + 8 * half;
                int bb = row >> 10, tt = row & 1023;
                float v0 = (acc[i][f][2 * half + 0] + b0) * oscale;
                float v1 = (acc[i][f][2 * half + 1] + b1) * oscale;
                if (z == 2) {
                    __half* dst = out + (size_t)(bb * H_ + hh) * HD_ * T_ + tt;
                    dst[(size_t)hd * T_]       = __float2half(v0);
                    dst[(size_t)(hd + 1) * T_] = __float2half(v1);
                } else {
                    *(__half2*)(out + ((size_t)(bb * H_ + hh) * T_ + tt) * HD_ + hd)
                        = __floats2half2_rn(v0, v1);
                }
            }
        }
}

// ============================================================
// Flash attention: fp16 K/V/Q, rel_bias via direct LDG,
// P kept entirely in registers (D-layout == A-frag layout for fp16 k16),
// 3-stage K/V cp.async ring.
// smem: 3 x (Ks 4608 + Vt 5120) + Ms 4096 = 33280 B
// ============================================================
#define ATT_STG_B 9728
__global__ __launch_bounds__(256, 2)
void attn_kernel(const float* __restrict__ rel_bias)
{
    extern __shared__ char smc[];
    float* Ms = (float*)(smc + 3 * ATT_STG_B);

    const int tid  = threadIdx.x;
    const int w    = tid >> 5;
    const int lane = tid & 31;
    const int g    = lane >> 2;
    const int q4   = lane & 3;
    const int qb   = 16 * w;
    const int q0   = blockIdx.x * 128;
    const int bh   = blockIdx.y;
    const int b    = bh / H_, h = bh % H_;

    const __half* qh  = g_q + (size_t)bh * T_ * HD_;
    const __half* kh  = g_k + (size_t)bh * T_ * HD_;
    const __half* vth = g_v + (size_t)bh * HD_ * T_;   // [hd][t]

    const int r0 = qb + g;
    const int r1 = qb + g + 8;

#define ATT_STAGE_LOAD(s, k0) do {                                             \
    char* Ks_ = smc + (s) * ATT_STG_B;                                         \
    char* Vt_ = Ks_ + 4608;                                                    \
    int kk = tid >> 3, ch = tid & 7;                                           \
    cp16(saddr(Ks_ + kk * 144 + ch * 16),                                      \
         kh + (size_t)((k0) + kk) * HD_ + ch * 8);                             \
    int hd = tid >> 2, cv = tid & 3;                                           \
    cp16(saddr(Vt_ + hd * 80 + cv * 16),                                       \
         vth + (size_t)hd * T_ + (k0) + cv * 8);                               \
    } while (0)

    ATT_STAGE_LOAD(0, 0);
    cp16(saddr(&Ms[tid * 4]), g_msk + (size_t)b * T_ + tid * 4);
    CP_COMMIT();
    ATT_STAGE_LOAD(1, 32);
    CP_COMMIT();
    ATT_STAGE_LOAD(2, 64);
    CP_COMMIT();

    // Q fragments
    uint32_t qf[4][4];
    {
        const uint32_t* qa = (const uint32_t*)(qh + (size_t)(q0 + r0) * HD_);
        const uint32_t* qc = (const uint32_t*)(qh + (size_t)(q0 + r1) * HD_);
#pragma unroll
        for (int c = 0; c < 4; c++) {
            qf[c][0] = qa[8 * c + q4];
            qf[c][1] = qc[8 * c + q4];
            qf[c][2] = qa[8 * c + 4 + q4];
            qf[c][3] = qc[8 * c + 4 + q4];
        }
    }
    const float ga0  = g_ga1[(size_t)bh * T_ + q0 + r0];
    const float ga1v = g_ga1[(size_t)bh * T_ + q0 + r1];

    const float* rbt = rel_bias + ((size_t)bh * T_ + 2 * q4) * T_ + q0;

    float l0 = 0.f, l1 = 0.f;
    float oacc[8][4];
#pragma unroll
    for (int f = 0; f < 8; f++)
#pragma unroll
        for (int e = 0; e < 4; e++) oacc[f][e] = 0.f;

    for (int kt = 0; kt < 32; kt++) {
        const int k0 = kt * 32;

        // ---- issue rel_bias LDGs (consumed after QK mmas) ----
        float rbv[4][4];
#pragma unroll
        for (int f = 0; f < 4; f++) {
            const float* p = rbt + (size_t)(k0 + 8 * f) * T_;
            rbv[f][0] = __ldg(p + r0);
            rbv[f][1] = __ldg(p + T_ + r0);
            rbv[f][2] = __ldg(p + r1);
            rbv[f][3] = __ldg(p + T_ + r1);
        }

        if (kt + 2 < 32) CP_WAIT2(); else CP_WAIT0();
        __syncthreads();
        const int slot = kt % 3;
        char* Ks = smc + slot * ATT_STG_B;
        char* Vt = Ks + 4608;
        const uint32_t kbase = saddr(Ks + lane * 144);
        const uint32_t vb0   = saddr(Vt + lane * 80);
        const uint32_t vb1   = saddr(Vt + (32 + lane) * 80);

        // ---- QK into zero-init sacc ----
        float sacc[4][4];
#pragma unroll
        for (int f = 0; f < 4; f++)
#pragma unroll
            for (int e = 0; e < 4; e++) sacc[f][e] = 0.f;
#pragma unroll
        for (int c = 0; c < 4; c++) {
            uint32_t bA[4], bB[4];
            LDSM_X4(bA, kbase + c * 32);
            LDSM_X4(bB, kbase + c * 32 + 16);
#pragma unroll
            for (int f = 0; f < 4; f++) {
                uint32_t bb2[2] = { bA[f], bB[f] };
                mma_f16(sacc[f], qf[c], bb2);
            }
        }

        // ---- P = exp2(qk + ga'*rb + msk') ; tree l-sum ----
#pragma unroll
        for (int f = 0; f < 4; f++) {
            int c0 = 8 * f + 2 * q4;
            sacc[f][0] = ex2(sacc[f][0] + fmaf(ga0,  rbv[f][0], Ms[k0 + c0]));
            sacc[f][1] = ex2(sacc[f][1] + fmaf(ga0,  rbv[f][1], Ms[k0 + c0 + 1]));
            sacc[f][2] = ex2(sacc[f][2] + fmaf(ga1v, rbv[f][2], Ms[k0 + c0]));
            sacc[f][3] = ex2(sacc[f][3] + fmaf(ga1v, rbv[f][3], Ms[k0 + c0 + 1]));
        }
        l0 += ((sacc[0][0] + sacc[0][1]) + (sacc[1][0] + sacc[1][1]))
            + ((sacc[2][0] + sacc[2][1]) + (sacc[3][0] + sacc[3][1]));
        l1 += ((sacc[0][2] + sacc[0][3]) + (sacc[1][2] + sacc[1][3]))
            + ((sacc[2][2] + sacc[2][3]) + (sacc[3][2] + sacc[3][3]));

        // ---- O += P @ V : P packed straight from sacc (no smem) ----
#pragma unroll
        for (int cc = 0; cc < 2; cc++) {
            uint32_t pa[4];
            pa[0] = h2u(__floats2half2_rn(sacc[2*cc][0],     sacc[2*cc][1]));
            pa[1] = h2u(__floats2half2_rn(sacc[2*cc][2],     sacc[2*cc][3]));
            pa[2] = h2u(__floats2half2_rn(sacc[2*cc + 1][0], sacc[2*cc + 1][1]));
            pa[3] = h2u(__floats2half2_rn(sacc[2*cc + 1][2], sacc[2*cc + 1][3]));
            uint32_t vA[4], vB[4], vC[4], vD[4];
            LDSM_X4(vA, vb0 + cc * 32);
            LDSM_X4(vB, vb0 + cc * 32 + 16);
            LDSM_X4(vC, vb1 + cc * 32);
            LDSM_X4(vD, vb1 + cc * 32 + 16);
#pragma unroll
            for (int f = 0; f < 4; f++) {
                uint32_t bb2[2] = { vA[f], vB[f] };
                mma_f16(oacc[f], pa, bb2);
            }
#pragma unroll
            for (int f = 0; f < 4; f++) {
                uint32_t bb2[2] = { vC[f], vD[f] };
                mma_f16(oacc[4 + f], pa, bb2);
            }
        }
        __syncthreads();
        if (kt + 3 < 32) { ATT_STAGE_LOAD(slot, (kt + 3) * 32); CP_COMMIT(); }
    }

    // ---- reduce l across quad, finalize: fp16 out ----
    l0 += __shfl_xor_sync(0xffffffffu, l0, 1);
    l0 += __shfl_xor_sync(0xffffffffu, l0, 2);
    l1 += __shfl_xor_sync(0xffffffffu, l1, 1);
    l1 += __shfl_xor_sync(0xffffffffu, l1, 2);
    float inv0 = 1.f / l0, inv1 = 1.f / l1;
#pragma unroll
    for (int f = 0; f < 8; f++) {
        int c = 8 * f + 2 * q4;
        size_t i0 = ((size_t)b * T_ + q0 + r0) * D_ + h * HD_ + c;
        size_t i1 = ((size_t)b * T_ + q0 + r1) * D_ + h * HD_ + c;
        *(__half2*)(g_o16 + i0) = __floats2half2_rn(oacc[f][0] * inv0, oacc[f][1] * inv0);
        *(__half2*)(g_o16 + i1) = __floats2half2_rn(oacc[f][2] * inv1, oacc[f][3] * inv1);
    }
}

// ============================================================
// O-proj GEMM, fp16 2-term (A.Bh + A.Bl) with ldmatrix.
// ============================================================
#define O2_STAGE 30720
__global__ __launch_bounds__(256, 2)
void gemm_o2(const __half* __restrict__ A,
             const __half* __restrict__ Bh, const __half* __restrict__ Bl,
             const float* __restrict__ bias, float* __restrict__ out)
{
    extern __shared__ char smo[];
    const int tid = threadIdx.x;
    const int w = tid >> 5, lane = tid & 31, g = lane >> 2, q4 = lane & 3;
    const int wm = (w & 1) * 64, wn = (w >> 1) * 32;
    const int row0 = blockIdx.x * 128, col0 = blockIdx.y * 128;

    float acc[4][4][4];
#pragma unroll
    for (int i = 0; i < 4; i++)
#pragma unroll
        for (int f = 0; f < 4; f++)
#pragma unroll
            for (int e = 0; e < 4; e++) acc[i][f][e] = 0.f;

    const int lrow = lane & 15;
    const int lchk = (lane >> 4) * 16;

#define O2_STAGE_LOAD(s, k0) do {                                              \
    char* base_ = smo + (s) * O2_STAGE;                                        \
    _Pragma("unroll")                                                          \
    for (int i = 0; i < 2; i++) {                                              \
        int idx = tid + i * 256;                                               \
        int r = idx >> 2, ch = idx & 3;                                        \
        uint32_t so = saddr(base_ + r * 80 + ch * 16);                         \
        cp16(so,         A  + (size_t)(row0 + r) * D_ + (k0) + ch * 8);        \
        cp16(so + 10240, Bh + (size_t)(col0 + r) * D_ + (k0) + ch * 8);        \
        cp16(so + 20480, Bl + (size_t)(col0 + r) * D_ + (k0) + ch * 8);        \
    } } while (0)

    O2_STAGE_LOAD(0, 0);  CP_COMMIT();
    O2_STAGE_LOAD(1, 32); CP_COMMIT();

    for (int kb = 0; kb < 24; kb++) {
        if (kb + 1 < 24) CP_WAIT1(); else CP_WAIT0();
        __syncthreads();
        char* base = smo + (kb & 1) * O2_STAGE;
#pragma unroll
        for (int ks = 0; ks < 2; ks++) {
            uint32_t ah[4][4];
#pragma unroll
            for (int i = 0; i < 4; i++)
                LDSM_X4(ah[i], saddr(base + (wm + 16 * i + lrow) * 80 + ks * 32 + lchk));
            uint32_t bh4[2][4], bl4[2][4];
#pragma unroll
            for (int j = 0; j < 2; j++) {
                uint32_t a = saddr(base + 10240 + (wn + 16 * j + lrow) * 80 + ks * 32 + lchk);
                LDSM_X4(bh4[j], a);
                LDSM_X4(bl4[j], a + 10240);
            }
#pragma unroll
            for (int i = 0; i < 4; i++)
#pragma unroll
                for (int f = 0; f < 4; f++) {
                    uint32_t bhf[2] = { bh4[f >> 1][f & 1], bh4[f >> 1][(f & 1) + 2] };
                    uint32_t blf[2] = { bl4[f >> 1][f & 1], bl4[f >> 1][(f & 1) + 2] };
                    mma_f16(acc[i][f], ah[i], bhf);
                    mma_f16(acc[i][f], ah[i], blf);
                }
        }
        __syncthreads();
        if (kb + 2 < 24) { O2_STAGE_LOAD(kb & 1, (kb + 2) * 32); CP_COMMIT(); }
    }

#pragma unroll
    for (int i = 0; i < 4; i++)
#pragma unroll
        for (int f = 0; f < 4; f++) {
            int col = col0 + wn + 8 * f + 2 * q4;
            float b0 = bias[col], b1 = bias[col + 1];
#pragma unroll
            for (int half = 0; half < 2; half++) {
                int row = row0 + wm + 16 * i + g + 8 * half;
                float2 v;
                v.x = acc[i][f][2 * half + 0] + b0;
                v.y = acc[i][f][2 * half + 1] + b1;
                *(float2*)(out + (size_t)row * D_ + col) = v;
            }
        }
}

// ============================================================
extern "C" void kernel_launch(void* const* d_in, const int* in_sizes, int n_in,
                              void* d_out, int out_size)
{
    const float* x         = (const float*)d_in[0];
    const float* attn_mask = (const float*)d_in[1];
    const float* rel_bias  = (const float*)d_in[2];
    const float* Wq = (const float*)d_in[3];
    const float* bq = (const float*)d_in[4];
    const float* Wk = (const float*)d_in[5];
    const float* bk = (const float*)d_in[6];
    const float* Wv = (const float*)d_in[7];
    const float* bv = (const float*)d_in[8];
    const float* Wo = (const float*)d_in[9];
    const float* bo = (const float*)d_in[10];
    const float* Wg = (const float*)d_in[11];
    const float* bg = (const float*)d_in[12];
    const float* grep_a = (const float*)d_in[13];
    float* out = (float*)d_out;

    __half *x16, *wt16, *woth, *wotl, *q, *k, *v, *o16;
    float *ga1;
    cudaGetSymbolAddress((void**)&x16,  g_x16);
    cudaGetSymbolAddress((void**)&wt16, g_wt16);
    cudaGetSymbolAddress((void**)&woth, g_woth);
    cudaGetSymbolAddress((void**)&wotl, g_wotl);
    cudaGetSymbolAddress((void**)&q,    g_q);
    cudaGetSymbolAddress((void**)&k,    g_k);
    cudaGetSymbolAddress((void**)&v,    g_v);
    cudaGetSymbolAddress((void**)&o16,  g_o16);
    cudaGetSymbolAddress((void**)&ga1,  g_ga1);

    cudaFuncSetAttribute(gemm_qkv16,  cudaFuncAttributeMaxDynamicSharedMemorySize, Q16_STAGE * 2);
    cudaFuncSetAttribute(attn_kernel, cudaFuncAttributeMaxDynamicSharedMemorySize, 33280);
    cudaFuncSetAttribute(gemm_o2,     cudaFuncAttributeMaxDynamicSharedMemorySize, O2_STAGE * 2);

    conv_all<<<NXB + 4 * NTB, 256>>>(                                                   // 0
        (const float4*)x, Wq, Wk, Wv, Wo, Wg, bg, x16, wt16, woth, wotl);
    gates_kernel<<<BH_ * T_ / 8, 256>>>(x, grep_a, attn_mask, ga1);                     // 1
    gemm_qkv16<<<dim3(64, 6, 3), 256, Q16_STAGE * 2>>>(                                 // 2
        x16, wt16, bq, bk, bv, q, k, v);
    attn_kernel<<<dim3(T_ / 128, BH_), 256, 33280>>>(rel_bias);                         // 3
    gemm_o2<<<dim3(64, 6), 256, O2_STAGE * 2>>>(o16, woth, wotl, bo, out);              // 4
}

// round 15
// speedup vs baseline: 1.5512x; 1.0102x over previous
#include <cuda_runtime.h>
#include <cuda_fp16.h>
#include <math.h>
#include <stdint.h>

#define B_  8
#define T_  1024
#define D_  768
#define H_  12
#define HD_ 64
#define BH_ (B_*H_)   /* 96 */
#define N_  (B_*T_)   /* 8192 */
#define WSZ_ ((size_t)D_*D_)
#define C_SM  (0.125f * 1.44269504088896340736f)   /* 0.125*log2(e) */
#define K8C   (1.44269504088896340736f)            /* log2(e) */

// ---- scratch (static device globals; no allocation) ----
__device__ __half g_x16[N_*D_];            // x fp16
__device__ __half g_wt16[3][D_*D_];        // Wq/Wk/Wv^T fp16 [n][k]
__device__ __half g_woth[D_*D_];           // Wo^T fp16 hi [n][k]
__device__ __half g_wotl[D_*D_];           // Wo^T fp16 lo
__device__ __half g_q[BH_*T_*HD_];         // fp16 (pre-scaled C_SM), [bh][t][hd]
__device__ __half g_k[BH_*T_*HD_];         // fp16, [bh][t][hd]
__device__ __half g_v[BH_*T_*HD_];         // fp16, TRANSPOSED [bh][hd][t]
__device__ __half g_o16[N_*D_];            // attn out fp16, row-major
__device__ float    g_ga1[BH_*T_];         // log2e * ga1
__device__ float    g_msk[N_];             // log2e * attn_mask
__device__ float    g_wg2[HD_*2];
__device__ float    g_bg2[2];

// ---- helpers ----
__device__ __forceinline__ float ex2(float x) {
    float r;
    asm("ex2.approx.f32 %0, %1;" : "=f"(r) : "f"(x));
    return r;
}
__device__ __forceinline__ void mma_f16(float* d, const uint32_t* a, const uint32_t* b) {
    asm volatile(
        "mma.sync.aligned.m16n8k16.row.col.f32.f16.f16.f32 "
        "{%0,%1,%2,%3}, {%4,%5,%6,%7}, {%8,%9}, {%0,%1,%2,%3};\n"
        : "+f"(d[0]), "+f"(d[1]), "+f"(d[2]), "+f"(d[3])
        : "r"(a[0]), "r"(a[1]), "r"(a[2]), "r"(a[3]), "r"(b[0]), "r"(b[1]));
}
#define LDSM_X4(r, a) \
    asm volatile("ldmatrix.sync.aligned.m8n8.x4.shared.b16 {%0,%1,%2,%3}, [%4];" \
        : "=r"((r)[0]), "=r"((r)[1]), "=r"((r)[2]), "=r"((r)[3]) : "r"(a))

__device__ __forceinline__ uint32_t saddr(const void* p) {
    return (uint32_t)__cvta_generic_to_shared(p);
}
__device__ __forceinline__ void cp16(uint32_t s, const void* g) {
    asm volatile("cp.async.cg.shared.global [%0], [%1], 16;\n" :: "r"(s), "l"(g));
}
#define CP_COMMIT() asm volatile("cp.async.commit_group;\n")
#define CP_WAIT2()  asm volatile("cp.async.wait_group 2;\n")
#define CP_WAIT1()  asm volatile("cp.async.wait_group 1;\n")
#define CP_WAIT0()  asm volatile("cp.async.wait_group 0;\n")

__device__ __forceinline__ uint32_t h2u(__half2 h) { return *(uint32_t*)&h; }

// ============================================================
// conv_all: x -> fp16 ; Wq/Wk/Wv -> W^T fp16 ; Wo -> W^T fp16 hi/lo;
// block 0: Wg row-sums.
// ============================================================
#define NXB 6144
#define NTB 576
__global__ __launch_bounds__(256)
void conv_all(const float4* __restrict__ x,
              const float* __restrict__ Wq, const float* __restrict__ Wk,
              const float* __restrict__ Wv, const float* __restrict__ Wo,
              const float* __restrict__ Wg, const float* __restrict__ bg,
              __half* __restrict__ x16, __half* __restrict__ wt16,
              __half* __restrict__ woth, __half* __restrict__ wotl)
{
    __shared__ float tile[32][33];
    const int bid = blockIdx.x, tid = threadIdx.x;

    if (bid == 0 && tid < 64) {
        int d = tid;
        const float* wg = Wg + d * 8;
        g_wg2[d * 2 + 0] = wg[0] + wg[1] + wg[2] + wg[3];
        g_wg2[d * 2 + 1] = wg[4] + wg[5] + wg[6] + wg[7];
        if (d == 0) {
            g_bg2[0] = bg[0] + bg[1] + bg[2] + bg[3];
            g_bg2[1] = bg[4] + bg[5] + bg[6] + bg[7];
        }
    }

    if (bid < NXB) {
        int i = bid * 256 + tid;
        float4 v = x[i];
        *(__half2*)(x16 + (size_t)i * 4)     = __floats2half2_rn(v.x, v.y);
        *(__half2*)(x16 + (size_t)i * 4 + 2) = __floats2half2_rn(v.z, v.w);
    } else {
        int r = bid - NXB;
        int z = r / NTB;                 // 0..3
        int bx = r % NTB;
        int n0 = (bx % 24) * 32, k0 = (bx / 24) * 32;
        const float* W = (z == 0) ? Wq : (z == 1) ? Wk : (z == 2) ? Wv : Wo;
        int tx = tid & 31, ty0 = tid >> 5;
#pragma unroll
        for (int j = 0; j < 4; j++)
            tile[ty0 + 8 * j][tx] = W[(size_t)(k0 + ty0 + 8 * j) * D_ + n0 + tx];
        __syncthreads();
#pragma unroll
        for (int j = 0; j < 4; j++) {
            int ty = ty0 + 8 * j;
            float f = tile[tx][ty];
            size_t o = (size_t)(n0 + ty) * D_ + k0 + tx;
            if (z < 3) {
                wt16[(size_t)z * WSZ_ + o] = __float2half(f);
            } else {
                __half h = __float2half(f);
                woth[o] = h;
                wotl[o] = __float2half(f - __half2float(h));
            }
        }
    }
}

// ============================================================
// Gates: emits log2e*ga1 ; also pre-scales the mask.
// ============================================================
__global__ __launch_bounds__(256)
void gates_kernel(const float* __restrict__ x, const float* __restrict__ grep_a,
                  const float* __restrict__ attn_mask, float* __restrict__ ga1)
{
    int gidx = blockIdx.x * 256 + threadIdx.x;
    if (gidx < N_) g_msk[gidx] = K8C * attn_mask[gidx];

    int w    = blockIdx.x * 8 + (threadIdx.x >> 5);
    int lane = threadIdx.x & 31;
    int bh = w >> 10, t = w & 1023;
    int b = bh / H_, h = bh % H_;
    const float* xp = x + ((size_t)b * T_ + t) * D_ + h * HD_;

    float s0 = 0.f, s1 = 0.f;
#pragma unroll
    for (int d = lane; d < HD_; d += 32) {
        float xv = xp[d];
        s0 += xv * g_wg2[d * 2 + 0];
        s1 += xv * g_wg2[d * 2 + 1];
    }
#pragma unroll
    for (int off = 16; off > 0; off >>= 1) {
        s0 += __shfl_xor_sync(0xffffffffu, s0, off);
        s1 += __shfl_xor_sync(0xffffffffu, s1, off);
    }
    if (lane == 0) {
        s0 += g_bg2[0];
        s1 += g_bg2[1];
        float ga = 1.f / (1.f + expf(-s0));
        float gb = 1.f / (1.f + expf(-s1));
        ga1[w] = K8C * (ga * (gb * grep_a[h] - 1.f) + 2.f);
    }
}

// ============================================================
// QKV GEMM, fp16 1-term, ldmatrix (proven kernel).
// ============================================================
#define Q16_STAGE 20480
__global__ __launch_bounds__(256, 2)
void gemm_qkv16(const __half* __restrict__ A, const __half* __restrict__ WT,
                const float* __restrict__ bb0, const float* __restrict__ bb1,
                const float* __restrict__ bb2,
                __half* __restrict__ o0, __half* __restrict__ o1,
                __half* __restrict__ o2)
{
    extern __shared__ char smq[];
    const int z = blockIdx.z;
    const __half* B = WT + (size_t)z * WSZ_;
    const float* bias = (z == 0) ? bb0 : (z == 1) ? bb1 : bb2;
    __half* out       = (z == 0) ? o0 : (z == 1) ? o1 : o2;
    const float oscale = (z == 0) ? C_SM : 1.f;

    const int tid = threadIdx.x;
    const int w = tid >> 5, lane = tid & 31, g = lane >> 2, q4 = lane & 3;
    const int wm = (w & 1) * 64, wn = (w >> 1) * 32;
    const int row0 = blockIdx.x * 128, col0 = blockIdx.y * 128;

    float acc[4][4][4];
#pragma unroll
    for (int i = 0; i < 4; i++)
#pragma unroll
        for (int f = 0; f < 4; f++)
#pragma unroll
            for (int e = 0; e < 4; e++) acc[i][f][e] = 0.f;

    const int lrow = lane & 15;
    const int lchk = (lane >> 4) * 16;

#define Q16_STAGE_LOAD(s, k0) do {                                             \
    char* base_ = smq + (s) * Q16_STAGE;                                       \
    _Pragma("unroll")                                                          \
    for (int i = 0; i < 2; i++) {                                              \
        int idx = tid + i * 256;                                               \
        int r = idx >> 2, ch = idx & 3;                                        \
        uint32_t so = saddr(base_ + r * 80 + ch * 16);                         \
        cp16(so,         A + (size_t)(row0 + r) * D_ + (k0) + ch * 8);         \
        cp16(so + 10240, B + (size_t)(col0 + r) * D_ + (k0) + ch * 8);         \
    } } while (0)

    Q16_STAGE_LOAD(0, 0);  CP_COMMIT();
    Q16_STAGE_LOAD(1, 32); CP_COMMIT();

    for (int kb = 0; kb < 24; kb++) {
        if (kb + 1 < 24) CP_WAIT1(); else CP_WAIT0();
        __syncthreads();
        char* base = smq + (kb & 1) * Q16_STAGE;
#pragma unroll
        for (int ks = 0; ks < 2; ks++) {
            uint32_t ah[4][4], bh4[2][4];
#pragma unroll
            for (int i = 0; i < 4; i++)
                LDSM_X4(ah[i], saddr(base + (wm + 16 * i + lrow) * 80 + ks * 32 + lchk));
#pragma unroll
            for (int j = 0; j < 2; j++)
                LDSM_X4(bh4[j], saddr(base + 10240 + (wn + 16 * j + lrow) * 80 + ks * 32 + lchk));
#pragma unroll
            for (int i = 0; i < 4; i++)
#pragma unroll
                for (int f = 0; f < 4; f++) {
                    uint32_t bf2[2] = { bh4[f >> 1][f & 1], bh4[f >> 1][(f & 1) + 2] };
                    mma_f16(acc[i][f], ah[i], bf2);
                }
        }
        __syncthreads();
        if (kb + 2 < 24) { Q16_STAGE_LOAD(kb & 1, (kb + 2) * 32); CP_COMMIT(); }
    }

#pragma unroll
    for (int i = 0; i < 4; i++)
#pragma unroll
        for (int f = 0; f < 4; f++) {
            int col = col0 + wn + 8 * f + 2 * q4;
            float b0 = bias[col], b1 = bias[col + 1];
            int hh = col >> 6, hd = col & 63;
#pragma unroll
            for (int half = 0; half < 2; half++) {
                int row = row0 + wm + 16 * i + g + 8 * half;
                int bb = row >> 10, tt = row & 1023;
                float v0 = (acc[i][f][2 * half + 0] + b0) * oscale;
                float v1 = (acc[i][f][2 * half + 1] + b1) * oscale;
                if (z == 2) {
                    __half* dst = out + (size_t)(bb * H_ + hh) * HD_ * T_ + tt;
                    dst[(size_t)hd * T_]       = __float2half(v0);
                    dst[(size_t)(hd + 1) * T_] = __float2half(v1);
                } else {
                    *(__half2*)(out + ((size_t)(bb * H_ + hh) * T_ + tt) * HD_ + hd)
                        = __floats2half2_rn(v0, v1);
                }
            }
        }
}

// ============================================================
// Flash attention: 128 threads, 4 warps x 32 q-rows (2 m-frags share
// every K/V fragment load). fp16 K/V/Q, P in registers, rb via LDG,
// 3-stage K/V cp.async ring.
// smem: 3 x (Ks 4608 + Vt 5120) + Ms 4096 = 33280 B
// ============================================================
#define ATT_STG_B 9728
__global__ __launch_bounds__(128, 2)
void attn_kernel(const float* __restrict__ rel_bias)
{
    extern __shared__ char smc[];
    float* Ms = (float*)(smc + 3 * ATT_STG_B);

    const int tid  = threadIdx.x;
    const int w    = tid >> 5;        // 0..3
    const int lane = tid & 31;
    const int g    = lane >> 2;
    const int q4   = lane & 3;
    const int qb   = 32 * w;          // warp owns q-rows [qb, qb+32)
    const int q0   = blockIdx.x * 128;
    const int bh   = blockIdx.y;
    const int b    = bh / H_, h = bh % H_;

    const __half* qh  = g_q + (size_t)bh * T_ * HD_;
    const __half* kh  = g_k + (size_t)bh * T_ * HD_;
    const __half* vth = g_v + (size_t)bh * HD_ * T_;   // [hd][t]

    const int r0 = qb + g;            // m=0 rows r0, r0+8 ; m=1 adds +16

#define ATT_STAGE_LOAD(s, k0) do {                                             \
    char* Ks_ = smc + (s) * ATT_STG_B;                                         \
    char* Vt_ = Ks_ + 4608;                                                    \
    int kk = tid >> 2, c2 = (tid & 3) * 2;                                     \
    cp16(saddr(Ks_ + kk * 144 + c2 * 16),                                      \
         kh + (size_t)((k0) + kk) * HD_ + c2 * 8);                             \
    cp16(saddr(Ks_ + kk * 144 + (c2 + 1) * 16),                                \
         kh + (size_t)((k0) + kk) * HD_ + (c2 + 1) * 8);                       \
    int hd = tid >> 1, cv = (tid & 1) * 2;                                     \
    cp16(saddr(Vt_ + hd * 80 + cv * 16),                                       \
         vth + (size_t)hd * T_ + (k0) + cv * 8);                               \
    cp16(saddr(Vt_ + hd * 80 + (cv + 1) * 16),                                 \
         vth + (size_t)hd * T_ + (k0) + (cv + 1) * 8);                         \
    } while (0)

    ATT_STAGE_LOAD(0, 0);
    cp16(saddr(&Ms[tid * 4]),       g_msk + (size_t)b * T_ + tid * 4);
    cp16(saddr(&Ms[512 + tid * 4]), g_msk + (size_t)b * T_ + 512 + tid * 4);
    CP_COMMIT();
    ATT_STAGE_LOAD(1, 32);
    CP_COMMIT();
    ATT_STAGE_LOAD(2, 64);
    CP_COMMIT();

    // Q fragments, both m-frags
    uint32_t qf[2][4][4];
#pragma unroll
    for (int m = 0; m < 2; m++) {
        const uint32_t* qa = (const uint32_t*)(qh + (size_t)(q0 + r0 + 16 * m) * HD_);
        const uint32_t* qc = (const uint32_t*)(qh + (size_t)(q0 + r0 + 16 * m + 8) * HD_);
#pragma unroll
        for (int c = 0; c < 4; c++) {
            qf[m][c][0] = qa[8 * c + q4];
            qf[m][c][1] = qc[8 * c + q4];
            qf[m][c][2] = qa[8 * c + 4 + q4];
            qf[m][c][3] = qc[8 * c + 4 + q4];
        }
    }
    float gav[2][2];
#pragma unroll
    for (int m = 0; m < 2; m++) {
        gav[m][0] = g_ga1[(size_t)bh * T_ + q0 + r0 + 16 * m];
        gav[m][1] = g_ga1[(size_t)bh * T_ + q0 + r0 + 16 * m + 8];
    }

    const float* rbt = rel_bias + ((size_t)bh * T_ + 2 * q4) * T_ + q0;

    float lsum[2][2] = {{0.f, 0.f}, {0.f, 0.f}};
    float oacc[2][8][4];
#pragma unroll
    for (int m = 0; m < 2; m++)
#pragma unroll
        for (int f = 0; f < 8; f++)
#pragma unroll
            for (int e = 0; e < 4; e++) oacc[m][f][e] = 0.f;

    for (int kt = 0; kt < 32; kt++) {
        const int k0 = kt * 32;

        // ---- issue rel_bias LDGs (both m-frags) ----
        float rbv[2][4][4];
#pragma unroll
        for (int f = 0; f < 4; f++) {
            const float* p = rbt + (size_t)(k0 + 8 * f) * T_;
#pragma unroll
            for (int m = 0; m < 2; m++) {
                rbv[m][f][0] = __ldg(p + r0 + 16 * m);
                rbv[m][f][1] = __ldg(p + T_ + r0 + 16 * m);
                rbv[m][f][2] = __ldg(p + r0 + 16 * m + 8);
                rbv[m][f][3] = __ldg(p + T_ + r0 + 16 * m + 8);
            }
        }

        if (kt + 2 < 32) CP_WAIT2(); else CP_WAIT0();
        __syncthreads();
        const int slot = kt % 3;
        char* Ks = smc + slot * ATT_STG_B;
        char* Vt = Ks + 4608;
        const uint32_t kbase = saddr(Ks + lane * 144);
        const uint32_t vb0   = saddr(Vt + lane * 80);
        const uint32_t vb1   = saddr(Vt + (32 + lane) * 80);

        // ---- QK: K frags shared across both m-frags ----
        float sacc[2][4][4];
#pragma unroll
        for (int m = 0; m < 2; m++)
#pragma unroll
            for (int f = 0; f < 4; f++)
#pragma unroll
                for (int e = 0; e < 4; e++) sacc[m][f][e] = 0.f;
#pragma unroll
        for (int c = 0; c < 4; c++) {
            uint32_t bA[4], bB[4];
            LDSM_X4(bA, kbase + c * 32);
            LDSM_X4(bB, kbase + c * 32 + 16);
#pragma unroll
            for (int m = 0; m < 2; m++)
#pragma unroll
                for (int f = 0; f < 4; f++) {
                    uint32_t bb2[2] = { bA[f], bB[f] };
                    mma_f16(sacc[m][f], qf[m][c], bb2);
                }
        }

        // ---- P = exp2(qk + ga'*rb + msk') ; partial l ----
#pragma unroll
        for (int m = 0; m < 2; m++) {
#pragma unroll
            for (int f = 0; f < 4; f++) {
                int c0 = 8 * f + 2 * q4;
                sacc[m][f][0] = ex2(sacc[m][f][0] + fmaf(gav[m][0], rbv[m][f][0], Ms[k0 + c0]));
                sacc[m][f][1] = ex2(sacc[m][f][1] + fmaf(gav[m][0], rbv[m][f][1], Ms[k0 + c0 + 1]));
                sacc[m][f][2] = ex2(sacc[m][f][2] + fmaf(gav[m][1], rbv[m][f][2], Ms[k0 + c0]));
                sacc[m][f][3] = ex2(sacc[m][f][3] + fmaf(gav[m][1], rbv[m][f][3], Ms[k0 + c0 + 1]));
            }
            lsum[m][0] += ((sacc[m][0][0] + sacc[m][0][1]) + (sacc[m][1][0] + sacc[m][1][1]))
                        + ((sacc[m][2][0] + sacc[m][2][1]) + (sacc[m][3][0] + sacc[m][3][1]));
            lsum[m][1] += ((sacc[m][0][2] + sacc[m][0][3]) + (sacc[m][1][2] + sacc[m][1][3]))
                        + ((sacc[m][2][2] + sacc[m][2][3]) + (sacc[m][3][2] + sacc[m][3][3]));
        }

        // ---- O += P @ V : V frags shared across both m-frags ----
#pragma unroll
        for (int cc = 0; cc < 2; cc++) {
            uint32_t vA[4], vB[4], vC[4], vD[4];
            LDSM_X4(vA, vb0 + cc * 32);
            LDSM_X4(vB, vb0 + cc * 32 + 16);
            LDSM_X4(vC, vb1 + cc * 32);
            LDSM_X4(vD, vb1 + cc * 32 + 16);
#pragma unroll
            for (int m = 0; m < 2; m++) {
                uint32_t pa[4];
                pa[0] = h2u(__floats2half2_rn(sacc[m][2*cc][0],     sacc[m][2*cc][1]));
                pa[1] = h2u(__floats2half2_rn(sacc[m][2*cc][2],     sacc[m][2*cc][3]));
                pa[2] = h2u(__floats2half2_rn(sacc[m][2*cc + 1][0], sacc[m][2*cc + 1][1]));
                pa[3] = h2u(__floats2half2_rn(sacc[m][2*cc + 1][2], sacc[m][2*cc + 1][3]));
#pragma unroll
                for (int f = 0; f < 4; f++) {
                    uint32_t bb2[2] = { vA[f], vB[f] };
                    mma_f16(oacc[m][f], pa, bb2);
                }
#pragma unroll
                for (int f = 0; f < 4; f++) {
                    uint32_t bb2[2] = { vC[f], vD[f] };
                    mma_f16(oacc[m][4 + f], pa, bb2);
                }
            }
        }
        __syncthreads();
        if (kt + 3 < 32) { ATT_STAGE_LOAD(slot, (kt + 3) * 32); CP_COMMIT(); }
    }

    // ---- reduce l across quad, finalize: fp16 out ----
#pragma unroll
    for (int m = 0; m < 2; m++) {
#pragma unroll
        for (int j = 0; j < 2; j++) {
            lsum[m][j] += __shfl_xor_sync(0xffffffffu, lsum[m][j], 1);
            lsum[m][j] += __shfl_xor_sync(0xffffffffu, lsum[m][j], 2);
        }
        float inv0 = 1.f / lsum[m][0], inv1 = 1.f / lsum[m][1];
#pragma unroll
        for (int f = 0; f < 8; f++) {
            int c = 8 * f + 2 * q4;
            size_t i0 = ((size_t)b * T_ + q0 + r0 + 16 * m) * D_ + h * HD_ + c;
            size_t i1 = ((size_t)b * T_ + q0 + r0 + 16 * m + 8) * D_ + h * HD_ + c;
            *(__half2*)(g_o16 + i0) = __floats2half2_rn(oacc[m][f][0] * inv0, oacc[m][f][1] * inv0);
            *(__half2*)(g_o16 + i1) = __floats2half2_rn(oacc[m][f][2] * inv1, oacc[m][f][3] * inv1);
        }
    }
}

// ============================================================
// O-proj GEMM, fp16 2-term (A.Bh + A.Bl) with ldmatrix.
// ============================================================
#define O2_STAGE 30720
__global__ __launch_bounds__(256, 2)
void gemm_o2(const __half* __restrict__ A,
             const __half* __restrict__ Bh, const __half* __restrict__ Bl,
             const float* __restrict__ bias, float* __restrict__ out)
{
    extern __shared__ char smo[];
    const int tid = threadIdx.x;
    const int w = tid >> 5, lane = tid & 31, g = lane >> 2, q4 = lane & 3;
    const int wm = (w & 1) * 64, wn = (w >> 1) * 32;
    const int row0 = blockIdx.x * 128, col0 = blockIdx.y * 128;

    float acc[4][4][4];
#pragma unroll
    for (int i = 0; i < 4; i++)
#pragma unroll
        for (int f = 0; f < 4; f++)
#pragma unroll
            for (int e = 0; e < 4; e++) acc[i][f][e] = 0.f;

    const int lrow = lane & 15;
    const int lchk = (lane >> 4) * 16;

#define O2_STAGE_LOAD(s, k0) do {                                              \
    char* base_ = smo + (s) * O2_STAGE;                                        \
    _Pragma("unroll")                                                          \
    for (int i = 0; i < 2; i++) {                                              \
        int idx = tid + i * 256;                                               \
        int r = idx >> 2, ch = idx & 3;                                        \
        uint32_t so = saddr(base_ + r * 80 + ch * 16);                         \
        cp16(so,         A  + (size_t)(row0 + r) * D_ + (k0) + ch * 8);        \
        cp16(so + 10240, Bh + (size_t)(col0 + r) * D_ + (k0) + ch * 8);        \
        cp16(so + 20480, Bl + (size_t)(col0 + r) * D_ + (k0) + ch * 8);        \
    } } while (0)

    O2_STAGE_LOAD(0, 0);  CP_COMMIT();
    O2_STAGE_LOAD(1, 32); CP_COMMIT();

    for (int kb = 0; kb < 24; kb++) {
        if (kb + 1 < 24) CP_WAIT1(); else CP_WAIT0();
        __syncthreads();
        char* base = smo + (kb & 1) * O2_STAGE;
#pragma unroll
        for (int ks = 0; ks < 2; ks++) {
            uint32_t ah[4][4];
#pragma unroll
            for (int i = 0; i < 4; i++)
                LDSM_X4(ah[i], saddr(base + (wm + 16 * i + lrow) * 80 + ks * 32 + lchk));
            uint32_t bh4[2][4], bl4[2][4];
#pragma unroll
            for (int j = 0; j < 2; j++) {
                uint32_t a = saddr(base + 10240 + (wn + 16 * j + lrow) * 80 + ks * 32 + lchk);
                LDSM_X4(bh4[j], a);
                LDSM_X4(bl4[j], a + 10240);
            }
#pragma unroll
            for (int i = 0; i < 4; i++)
#pragma unroll
                for (int f = 0; f < 4; f++) {
                    uint32_t bhf[2] = { bh4[f >> 1][f & 1], bh4[f >> 1][(f & 1) + 2] };
                    uint32_t blf[2] = { bl4[f >> 1][f & 1], bl4[f >> 1][(f & 1) + 2] };
                    mma_f16(acc[i][f], ah[i], bhf);
                    mma_f16(acc[i][f], ah[i], blf);
                }
        }
        __syncthreads();
        if (kb + 2 < 24) { O2_STAGE_LOAD(kb & 1, (kb + 2) * 32); CP_COMMIT(); }
    }

#pragma unroll
    for (int i = 0; i < 4; i++)
#pragma unroll
        for (int f = 0; f < 4; f++) {
            int col = col0 + wn + 8 * f + 2 * q4;
            float b0 = bias[col], b1 = bias[col + 1];
#pragma unroll
            for (int half = 0; half < 2; half++) {
                int row = row0 + wm + 16 * i + g + 8 * half;
                float2 v;
                v.x = acc[i][f][2 * half + 0] + b0;
                v.y = acc[i][f][2 * half + 1] + b1;
                *(float2*)(out + (size_t)row * D_ + col) = v;
            }
        }
}

// ============================================================
extern "C" void kernel_launch(void* const* d_in, const int* in_sizes, int n_in,
                              void* d_out, int out_size)
{
    const float* x         = (const float*)d_in[0];
    const float* attn_mask = (const float*)d_in[1];
    const float* rel_bias  = (const float*)d_in[2];
    const float* Wq = (const float*)d_in[3];
    const float* bq = (const float*)d_in[4];
    const float* Wk = (const float*)d_in[5];
    const float* bk = (const float*)d_in[6];
    const float* Wv = (const float*)d_in[7];
    const float* bv = (const float*)d_in[8];
    const float* Wo = (const float*)d_in[9];
    const float* bo = (const float*)d_in[10];
    const float* Wg = (const float*)d_in[11];
    const float* bg = (const float*)d_in[12];
    const float* grep_a = (const float*)d_in[13];
    float* out = (float*)d_out;

    __half *x16, *wt16, *woth, *wotl, *q, *k, *v, *o16;
    float *ga1;
    cudaGetSymbolAddress((void**)&x16,  g_x16);
    cudaGetSymbolAddress((void**)&wt16, g_wt16);
    cudaGetSymbolAddress((void**)&woth, g_woth);
    cudaGetSymbolAddress((void**)&wotl, g_wotl);
    cudaGetSymbolAddress((void**)&q,    g_q);
    cudaGetSymbolAddress((void**)&k,    g_k);
    cudaGetSymbolAddress((void**)&v,    g_v);
    cudaGetSymbolAddress((void**)&o16,  g_o16);
    cudaGetSymbolAddress((void**)&ga1,  g_ga1);

    cudaFuncSetAttribute(gemm_qkv16,  cudaFuncAttributeMaxDynamicSharedMemorySize, Q16_STAGE * 2);
    cudaFuncSetAttribute(attn_kernel, cudaFuncAttributeMaxDynamicSharedMemorySize, 33280);
    cudaFuncSetAttribute(gemm_o2,     cudaFuncAttributeMaxDynamicSharedMemorySize, O2_STAGE * 2);

    conv_all<<<NXB + 4 * NTB, 256>>>(                                                   // 0
        (const float4*)x, Wq, Wk, Wv, Wo, Wg, bg, x16, wt16, woth, wotl);
    gates_kernel<<<BH_ * T_ / 8, 256>>>(x, grep_a, attn_mask, ga1);                     // 1
    gemm_qkv16<<<dim3(64, 6, 3), 256, Q16_STAGE * 2>>>(                                 // 2
        x16, wt16, bq, bk, bv, q, k, v);
    attn_kernel<<<dim3(T_ / 128, BH_), 128, 33280>>>(rel_bias);                         // 3
    gemm_o2<<<dim3(64, 6), 256, O2_STAGE * 2>>>(o16, woth, wotl, bo, out);              // 4
}